// round 2
// baseline (speedup 1.0000x reference)
#include <cuda_runtime.h>
#include <cuda.h>
#include <cstdint>
#include <cstddef>

// Problem dims
#define MDIM 8192
#define NDIM 4096
#define KDIM 4096
#define BLK  32

// GEMM tiling
#define TM 128
#define TN 256
#define KT 32                 // fp32 elements per K-chunk = one 128B SW128 row
#define NSTAGES 4
#define NKITER (KDIM / KT)    // 128

#define A_BYTES (TM * KT * 4)         // 16384
#define B_BYTES (TN * KT * 4)         // 32768
#define STAGE_BYTES (A_BYTES + B_BYTES)               // 49152
#define SMEM_DATA0 1024
#define SMEM_TOTAL (SMEM_DATA0 + NSTAGES * STAGE_BYTES)  // 197632

#define OFF_FULL(s)  (16 + (s) * 8)

// Scratch: tf32-rounded operands (static device globals: allowed, no runtime alloc)
__device__ float g_wm[(size_t)NDIM * (size_t)KDIM];   // masked + tf32-rounded W
__device__ float g_xt[(size_t)MDIM * (size_t)KDIM];   // tf32-rounded x

// ---------------- device helpers ----------------

__device__ __forceinline__ uint32_t smem_u32(const void* p) {
  uint32_t r;
  asm("{ .reg .u64 t; cvta.to.shared.u64 t, %1; cvt.u32.u64 %0, t; }"
      : "=r"(r) : "l"(p));
  return r;
}

__device__ __forceinline__ void mbar_init(uint32_t a, uint32_t cnt) {
  asm volatile("mbarrier.init.shared::cta.b64 [%0], %1;"
               :: "r"(a), "r"(cnt) : "memory");
}
__device__ __forceinline__ void mbar_expect_tx(uint32_t a, uint32_t bytes) {
  asm volatile("mbarrier.arrive.expect_tx.shared::cta.b64 _, [%0], %1;"
               :: "r"(a), "r"(bytes) : "memory");
}
__device__ __forceinline__ void mbar_wait(uint32_t a, uint32_t parity) {
  asm volatile(
      "{\n\t.reg .pred P;\n\t"
      "WL%=:\n\t"
      "mbarrier.try_wait.parity.acquire.cta.shared::cta.b64 P, [%0], %1, 0x989680;\n\t"
      "@P bra WD%=;\n\t"
      "bra WL%=;\n\t"
      "WD%=:\n\t}"
      :: "r"(a), "r"(parity) : "memory");
}

__device__ __forceinline__ void tma_load_2d(uint32_t smem_dst, const void* map,
                                            int cx, int cy, uint32_t bar) {
  asm volatile(
      "cp.async.bulk.tensor.2d.shared::cta.global.tile.mbarrier::complete_tx::bytes "
      "[%0], [%1, {%2, %3}], [%4];"
      :: "r"(smem_dst), "l"(map), "r"(cx), "r"(cy), "r"(bar) : "memory");
}

__device__ __forceinline__ uint32_t f2tf32(float f) {
  uint32_t u;
  asm("cvt.rna.tf32.f32 %0, %1;" : "=r"(u) : "f"(f));
  return u;
}

__device__ __forceinline__ void mma_tf32(float* c, const uint32_t* a,
                                         const uint32_t* b) {
  asm volatile(
      "mma.sync.aligned.m16n8k8.row.col.f32.tf32.tf32.f32 "
      "{%0,%1,%2,%3}, {%4,%5,%6,%7}, {%8,%9}, {%0,%1,%2,%3};"
      : "+f"(c[0]), "+f"(c[1]), "+f"(c[2]), "+f"(c[3])
      : "r"(a[0]), "r"(a[1]), "r"(a[2]), "r"(a[3]), "r"(b[0]), "r"(b[1]));
}

// ---------------- pre-pass kernels ----------------

// W_masked = tf32(W * repeat(block_mask)); float4-vectorized.
__global__ void __launch_bounds__(256)
premask_kernel(const float4* __restrict__ w, const int* __restrict__ bm,
               float* __restrict__ wm) {
  int i = blockIdx.x * 256 + threadIdx.x;       // 0 .. NDIM*KDIM/4-1
  float4 v = w[i];
  int e = i << 2;
  int o = e >> 12;                               // / KDIM
  int k = e & (KDIM - 1);
  uint4 r;
  if (bm[((o >> 5) << 7) + (k >> 5)] == 0) {
    r = make_uint4(0u, 0u, 0u, 0u);
  } else {
    r.x = f2tf32(v.x); r.y = f2tf32(v.y); r.z = f2tf32(v.z); r.w = f2tf32(v.w);
  }
  reinterpret_cast<uint4*>(wm)[i] = r;
}

// x_t = tf32(x)
__global__ void __launch_bounds__(256)
cvtx_kernel(const float4* __restrict__ x, float* __restrict__ xt) {
  int i = blockIdx.x * 256 + threadIdx.x;
  float4 v = x[i];
  uint4 r;
  r.x = f2tf32(v.x); r.y = f2tf32(v.y); r.z = f2tf32(v.z); r.w = f2tf32(v.w);
  reinterpret_cast<uint4*>(xt)[i] = r;
}

// ---------------- GEMM kernel ----------------
// CTA 128x256, 8 warps (2x4 grid of 64x64 warp tiles), tf32 mma.sync m16n8k8.
// TMA + mbarrier 4-stage pipeline; SW128 swizzled SMEM; conflict-free LDS.

__global__ void __launch_bounds__(256, 1)
bsl_gemm_kernel(const __grid_constant__ CUtensorMap tmA,
                const __grid_constant__ CUtensorMap tmB,
                const float* __restrict__ bias,
                float* __restrict__ out) {
  extern __shared__ char smem[];
  const uint32_t sb = smem_u32(smem);
  const int tid  = threadIdx.x;
  const int w    = tid >> 5;
  const int lane = tid & 31;
  const int grp  = lane >> 2;        // 0..7
  const int c4   = lane & 3;         // 0..3

  const int m0 = blockIdx.x * TM;
  const int n0 = blockIdx.y * TN;

  if (tid == 0) {
    #pragma unroll
    for (int s = 0; s < NSTAGES; s++) mbar_init(sb + OFF_FULL(s), 1);
    asm volatile("fence.proxy.async.shared::cta;" ::: "memory");
  }
  __syncthreads();

  // Prologue: fill all stages
  if (tid == 0) {
    #pragma unroll
    for (int s = 0; s < NSTAGES; s++) {
      mbar_expect_tx(sb + OFF_FULL(s), STAGE_BYTES);
      uint32_t a_dst = sb + SMEM_DATA0 + s * STAGE_BYTES;
      tma_load_2d(a_dst, &tmA, s * KT, m0, sb + OFF_FULL(s));
      tma_load_2d(a_dst + A_BYTES, &tmB, s * KT, n0, sb + OFF_FULL(s));
    }
  }

  // Per-thread fragment addressing.
  // SW128 within a 128B row: element (row, col) lives at row*128 + ((col*4) ^ ((row&7)*16)).
  // All our fragment rows satisfy (row & 7) == grp, so the XOR term is grp*16.
  const uint32_t grp16 = grp << 4;
  const int wm = (w >> 2) * 64;      // warp m offset within tile
  const int wn = (w & 3) * 64;       // warp n offset within tile
  uint32_t arow[4], brow[8];
  #pragma unroll
  for (int mt = 0; mt < 4; mt++) arow[mt] = (wm + mt * 16 + grp) * 128;
  #pragma unroll
  for (int nt = 0; nt < 8; nt++) brow[nt] = (wn + nt * 8 + grp) * 128;
  const uint32_t c44 = c4 << 2;

  float acc[4][8][4];
  #pragma unroll
  for (int mt = 0; mt < 4; mt++)
    #pragma unroll
    for (int nt = 0; nt < 8; nt++)
      #pragma unroll
      for (int r = 0; r < 4; r++) acc[mt][nt][r] = 0.f;

  for (int kb = 0; kb < NKITER; kb++) {
    const int st = kb & (NSTAGES - 1);
    const int ph = (kb / NSTAGES) & 1;
    mbar_wait(sb + OFF_FULL(st), ph);

    const char* As = smem + SMEM_DATA0 + st * STAGE_BYTES;
    const char* Bs = As + A_BYTES;

    #pragma unroll
    for (int ks = 0; ks < 4; ks++) {
      const uint32_t cx0 = ((uint32_t)(ks * 32) | c44) ^ grp16;
      const uint32_t cx1 = ((uint32_t)(ks * 32) | c44 | 16u) ^ grp16;
      uint32_t a[4][4];
      #pragma unroll
      for (int mt = 0; mt < 4; mt++) {
        a[mt][0] = *reinterpret_cast<const uint32_t*>(As + arow[mt] + cx0);
        a[mt][1] = *reinterpret_cast<const uint32_t*>(As + arow[mt] + 1024 + cx0);
        a[mt][2] = *reinterpret_cast<const uint32_t*>(As + arow[mt] + cx1);
        a[mt][3] = *reinterpret_cast<const uint32_t*>(As + arow[mt] + 1024 + cx1);
      }
      uint32_t b[8][2];
      #pragma unroll
      for (int nt = 0; nt < 8; nt++) {
        b[nt][0] = *reinterpret_cast<const uint32_t*>(Bs + brow[nt] + cx0);
        b[nt][1] = *reinterpret_cast<const uint32_t*>(Bs + brow[nt] + cx1);
      }
      #pragma unroll
      for (int mt = 0; mt < 4; mt++)
        #pragma unroll
        for (int nt = 0; nt < 8; nt++)
          mma_tf32(acc[mt][nt], a[mt], b[nt]);
    }

    __syncthreads();   // all warps done with stage st
    if (tid == 0 && kb + NSTAGES < NKITER) {
      mbar_expect_tx(sb + OFF_FULL(st), STAGE_BYTES);
      uint32_t a_dst = sb + SMEM_DATA0 + st * STAGE_BYTES;
      tma_load_2d(a_dst, &tmA, (kb + NSTAGES) * KT, m0, sb + OFF_FULL(st));
      tma_load_2d(a_dst + A_BYTES, &tmB, (kb + NSTAGES) * KT, n0,
                  sb + OFF_FULL(st));
    }
  }

  // Epilogue: D layout per mma tile: c0,c1 -> (row g, col 2*c4 .. +1);
  // c2,c3 -> (row g+8, same cols).
  #pragma unroll
  for (int nt = 0; nt < 8; nt++) {
    const int col = n0 + wn + nt * 8 + c4 * 2;
    const float2 bv = *reinterpret_cast<const float2*>(bias + col);
    #pragma unroll
    for (int mt = 0; mt < 4; mt++) {
      const int row = m0 + wm + mt * 16 + grp;
      float2 o0, o1;
      o0.x = acc[mt][nt][0] + bv.x;
      o0.y = acc[mt][nt][1] + bv.y;
      o1.x = acc[mt][nt][2] + bv.x;
      o1.y = acc[mt][nt][3] + bv.y;
      *reinterpret_cast<float2*>(out + (size_t)row * NDIM + col) = o0;
      *reinterpret_cast<float2*>(out + (size_t)(row + 8) * NDIM + col) = o1;
    }
  }
}

// ---------------- host launch ----------------

typedef CUresult (*EncodeTiledFn)(
    CUtensorMap*, CUtensorMapDataType, cuuint32_t, void*, const cuuint64_t*,
    const cuuint64_t*, const cuuint32_t*, const cuuint32_t*,
    CUtensorMapInterleave, CUtensorMapSwizzle, CUtensorMapL2promotion,
    CUtensorMapFloatOOBfill);

extern "C" void kernel_launch(void* const* d_in, const int* in_sizes, int n_in,
                              void* d_out, int out_size) {
  // Identify inputs by element count (robust to ordering)
  const float* x = nullptr;
  const float* wgt = nullptr;
  const float* bias = nullptr;
  const int* bm = nullptr;
  for (int i = 0; i < n_in; i++) {
    long long sz = in_sizes[i];
    if (sz == (long long)MDIM * KDIM)       x    = (const float*)d_in[i];
    else if (sz == (long long)NDIM * KDIM)  wgt  = (const float*)d_in[i];
    else if (sz == NDIM)                    bias = (const float*)d_in[i];
    else if (sz == (NDIM / BLK) * (KDIM / BLK)) bm = (const int*)d_in[i];
  }

  void* wm_ptr = nullptr;
  void* xt_ptr = nullptr;
  cudaGetSymbolAddress(&wm_ptr, g_wm);
  cudaGetSymbolAddress(&xt_ptr, g_xt);

  // 1) Pre-pass: mask + tf32-round W; tf32-round x.
  premask_kernel<<<(NDIM * KDIM / 4) / 256, 256>>>(
      (const float4*)wgt, bm, (float*)wm_ptr);
  cvtx_kernel<<<((size_t)MDIM * KDIM / 4) / 256, 256>>>(
      (const float4*)x, (float*)xt_ptr);

  // 2) TMA descriptors (driver entry point via runtime; no -lcuda link)
  EncodeTiledFn enc = nullptr;
  cudaDriverEntryPointQueryResult qr;
  cudaGetDriverEntryPoint("cuTensorMapEncodeTiled", (void**)&enc,
                          cudaEnableDefault, &qr);

  CUtensorMap tmA, tmB;
  {
    cuuint64_t dims[2]    = {(cuuint64_t)KDIM, (cuuint64_t)MDIM};
    cuuint64_t strides[1] = {(cuuint64_t)KDIM * sizeof(float)};
    cuuint32_t box[2]     = {KT, TM};       // 32 f32 = 128B rows (SW128 atom)
    cuuint32_t es[2]      = {1, 1};
    enc(&tmA, CU_TENSOR_MAP_DATA_TYPE_FLOAT32, 2, xt_ptr, dims, strides, box,
        es, CU_TENSOR_MAP_INTERLEAVE_NONE, CU_TENSOR_MAP_SWIZZLE_128B,
        CU_TENSOR_MAP_L2_PROMOTION_L2_128B, CU_TENSOR_MAP_FLOAT_OOB_FILL_NONE);
  }
  {
    cuuint64_t dims[2]    = {(cuuint64_t)KDIM, (cuuint64_t)NDIM};
    cuuint64_t strides[1] = {(cuuint64_t)KDIM * sizeof(float)};
    cuuint32_t box[2]     = {KT, TN};
    cuuint32_t es[2]      = {1, 1};
    enc(&tmB, CU_TENSOR_MAP_DATA_TYPE_FLOAT32, 2, wm_ptr, dims, strides, box,
        es, CU_TENSOR_MAP_INTERLEAVE_NONE, CU_TENSOR_MAP_SWIZZLE_128B,
        CU_TENSOR_MAP_L2_PROMOTION_L2_128B, CU_TENSOR_MAP_FLOAT_OOB_FILL_NONE);
  }

  // 3) GEMM
  cudaFuncSetAttribute(bsl_gemm_kernel,
                       cudaFuncAttributeMaxDynamicSharedMemorySize, SMEM_TOTAL);
  dim3 grid(MDIM / TM, NDIM / TN);   // 64 x 16
  bsl_gemm_kernel<<<grid, 256, SMEM_TOTAL>>>(tmA, tmB, bias, (float*)d_out);
}

// round 3
// speedup vs baseline: 1.1780x; 1.1780x over previous
#include <cuda_runtime.h>
#include <cuda.h>
#include <cstdint>
#include <cstddef>

// Problem dims
#define MDIM 8192
#define NDIM 4096
#define KDIM 4096
#define BLK  32

// GEMM tiling
#define TM 128
#define TN 256
#define KT 32                 // fp32 elements per K-chunk = one K-block = 128B row
#define NSTAGES 4
#define NKITER (KDIM / KT)    // 128
#define NWC 8                 // compute warps
#define THREADS 288           // 8 compute warps + 1 producer warp

#define A_BYTES (TM * KT * 4)         // 16384
#define B_BYTES (TN * KT * 4)         // 32768
#define BBLK_BYTES (32 * KT * 4)      // 4096 per n-block
#define STAGE_BYTES (A_BYTES + B_BYTES)               // 49152
#define SMEM_DATA0 1024
#define SMEM_TOTAL (SMEM_DATA0 + NSTAGES * STAGE_BYTES)  // 197632

#define OFF_FULL(s)  (16 + (s) * 8)
#define OFF_EMPTY(s) (64 + (s) * 8)
#define OFF_LIVE     512              // 128 bytes: live mask per k-block

// Scratch (static device globals: allowed, no runtime alloc)
__device__ float g_wm[(size_t)NDIM * (size_t)KDIM];   // masked+tf32+col-permuted W
__device__ float g_xt[(size_t)MDIM * (size_t)KDIM];   // tf32+col-permuted x
__device__ unsigned char g_live[(NDIM / TN) * NKITER];  // [16][128]

// ---------------- device helpers ----------------

__device__ __forceinline__ uint32_t smem_u32(const void* p) {
  uint32_t r;
  asm("{ .reg .u64 t; cvta.to.shared.u64 t, %1; cvt.u32.u64 %0, t; }"
      : "=r"(r) : "l"(p));
  return r;
}
__device__ __forceinline__ void mbar_init(uint32_t a, uint32_t cnt) {
  asm volatile("mbarrier.init.shared::cta.b64 [%0], %1;"
               :: "r"(a), "r"(cnt) : "memory");
}
__device__ __forceinline__ void mbar_expect_tx(uint32_t a, uint32_t bytes) {
  asm volatile("mbarrier.arrive.expect_tx.shared::cta.b64 _, [%0], %1;"
               :: "r"(a), "r"(bytes) : "memory");
}
__device__ __forceinline__ void mbar_arrive(uint32_t a) {
  asm volatile("mbarrier.arrive.shared::cta.b64 _, [%0];"
               :: "r"(a) : "memory");
}
__device__ __forceinline__ void mbar_wait(uint32_t a, uint32_t parity) {
  asm volatile(
      "{\n\t.reg .pred P;\n\t"
      "WL%=:\n\t"
      "mbarrier.try_wait.parity.acquire.cta.shared::cta.b64 P, [%0], %1, 0x989680;\n\t"
      "@P bra WD%=;\n\t"
      "bra WL%=;\n\t"
      "WD%=:\n\t}"
      :: "r"(a), "r"(parity) : "memory");
}
__device__ __forceinline__ void tma_load_2d(uint32_t smem_dst, const void* map,
                                            int cx, int cy, uint32_t bar) {
  asm volatile(
      "cp.async.bulk.tensor.2d.shared::cta.global.tile.mbarrier::complete_tx::bytes "
      "[%0], [%1, {%2, %3}], [%4];"
      :: "r"(smem_dst), "l"(map), "r"(cx), "r"(cy), "r"(bar) : "memory");
}
__device__ __forceinline__ uint32_t f2tf32(float f) {
  uint32_t u;
  asm("cvt.rna.tf32.f32 %0, %1;" : "=r"(u) : "f"(f));
  return u;
}
__device__ __forceinline__ void mma_tf32(float* c, uint32_t a0, uint32_t a1,
                                         uint32_t a2, uint32_t a3,
                                         uint32_t b0, uint32_t b1) {
  asm volatile(
      "mma.sync.aligned.m16n8k8.row.col.f32.tf32.tf32.f32 "
      "{%0,%1,%2,%3}, {%4,%5,%6,%7}, {%8,%9}, {%0,%1,%2,%3};"
      : "+f"(c[0]), "+f"(c[1]), "+f"(c[2]), "+f"(c[3])
      : "r"(a0), "r"(a1), "r"(a2), "r"(a3), "r"(b0), "r"(b1));
}

// ---------------- pre-pass kernels ----------------
// Column-pair permutation within each 8-col k-group: old pos w -> (w<4 ? 2w : 2(w-4)+1).
// Makes fragment pairs (col c4, col c4+4) adjacent -> LDS.64 in the GEMM.
// Permutation stays within one 32-col k-block, so mask indexing is unchanged.

// W: mask + tf32-round + permute. One thread per 8-element k-group.
__global__ void __launch_bounds__(256)
premask_kernel(const float4* __restrict__ w, const int* __restrict__ bm,
               float* __restrict__ wm) {
  int i = blockIdx.x * 256 + threadIdx.x;        // group index
  int o = i >> 9;                                 // row (KDIM/8 = 512 groups/row)
  int k = (i & 511) << 3;                         // col of group start
  float4 lo = w[i * 2], hi = w[i * 2 + 1];
  uint4 o0, o1;
  if (bm[((o >> 5) << 7) + (k >> 5)] == 0) {
    o0 = make_uint4(0u, 0u, 0u, 0u);
    o1 = o0;
  } else {
    o0.x = f2tf32(lo.x); o0.y = f2tf32(hi.x);
    o0.z = f2tf32(lo.y); o0.w = f2tf32(hi.y);
    o1.x = f2tf32(lo.z); o1.y = f2tf32(hi.z);
    o1.z = f2tf32(lo.w); o1.w = f2tf32(hi.w);
  }
  reinterpret_cast<uint4*>(wm)[i * 2]     = o0;
  reinterpret_cast<uint4*>(wm)[i * 2 + 1] = o1;
}

// x: tf32-round + permute.
__global__ void __launch_bounds__(256)
cvtx_kernel(const float4* __restrict__ x, float* __restrict__ xt) {
  int i = blockIdx.x * 256 + threadIdx.x;
  float4 lo = x[i * 2], hi = x[i * 2 + 1];
  uint4 o0, o1;
  o0.x = f2tf32(lo.x); o0.y = f2tf32(hi.x);
  o0.z = f2tf32(lo.y); o0.w = f2tf32(hi.y);
  o1.x = f2tf32(lo.z); o1.y = f2tf32(hi.z);
  o1.z = f2tf32(lo.w); o1.w = f2tf32(hi.w);
  reinterpret_cast<uint4*>(xt)[i * 2]     = o0;
  reinterpret_cast<uint4*>(xt)[i * 2 + 1] = o1;
}

// Live mask: per (n-tile cn, k-block kb), bit j = block (cn*8+j, kb) nonzero.
__global__ void __launch_bounds__(256)
livemask_kernel(const int* __restrict__ bm, unsigned char* __restrict__ lv) {
  int t = blockIdx.x * 256 + threadIdx.x;   // 0..2047
  int cn = t >> 7, kb = t & 127;
  unsigned b = 0;
  #pragma unroll
  for (int j = 0; j < 8; j++)
    b |= (bm[(cn * 8 + j) * 128 + kb] ? 1u : 0u) << j;
  lv[t] = (unsigned char)b;
}

// ---------------- GEMM ----------------
// CTA 128x256, 8 compute warps (2x4 grid of 64x64 warp tiles) + 1 producer warp.
// tf32 mma.sync m16n8k8; TMA+mbarrier 4-stage pipeline; per-n-block B loads with
// sparsity skipping; warps run independently (empty barriers, count=8).

template <bool L0, bool L1>
__device__ __forceinline__ void stage_mma(const char* As, const char* Bs,
                                          const uint32_t* arow,
                                          const uint32_t* brow,
                                          uint32_t xorb,
                                          float acc[4][8][4]) {
  #pragma unroll
  for (int ks = 0; ks < 4; ks++) {
    const uint32_t cx = ((uint32_t)(ks * 32)) ^ xorb;
    uint2 p0[4], p1[4];
    #pragma unroll
    for (int mt = 0; mt < 4; mt++) {
      p0[mt] = *reinterpret_cast<const uint2*>(As + arow[mt] + cx);
      p1[mt] = *reinterpret_cast<const uint2*>(As + arow[mt] + 1024 + cx);
    }
    if (L0) {
      uint2 b[4];
      #pragma unroll
      for (int nt = 0; nt < 4; nt++)
        b[nt] = *reinterpret_cast<const uint2*>(Bs + brow[nt] + cx);
      #pragma unroll
      for (int mt = 0; mt < 4; mt++)
        #pragma unroll
        for (int nt = 0; nt < 4; nt++)
          mma_tf32(acc[mt][nt], p0[mt].x, p1[mt].x, p0[mt].y, p1[mt].y,
                   b[nt].x, b[nt].y);
    }
    if (L1) {
      uint2 b[4];
      #pragma unroll
      for (int nt = 0; nt < 4; nt++)
        b[nt] = *reinterpret_cast<const uint2*>(Bs + brow[nt + 4] + cx);
      #pragma unroll
      for (int mt = 0; mt < 4; mt++)
        #pragma unroll
        for (int nt = 0; nt < 4; nt++)
          mma_tf32(acc[mt][nt + 4], p0[mt].x, p1[mt].x, p0[mt].y, p1[mt].y,
                   b[nt].x, b[nt].y);
    }
  }
}

__global__ void __launch_bounds__(THREADS, 1)
bsl_gemm_kernel(const __grid_constant__ CUtensorMap tmA,
                const __grid_constant__ CUtensorMap tmB,
                const float* __restrict__ bias,
                float* __restrict__ out) {
  extern __shared__ char smem[];
  const uint32_t sb = smem_u32(smem);
  const int tid  = threadIdx.x;
  const int w    = tid >> 5;
  const int lane = tid & 31;
  const int grp  = lane >> 2;
  const int c4   = lane & 3;

  // grid: x = n-tile (16), y = m-tile (64)  -> wave-blocked for L2 reuse
  const int n0 = blockIdx.x * TN;
  const int m0 = blockIdx.y * TM;

  if (tid == 0) {
    #pragma unroll
    for (int s = 0; s < NSTAGES; s++) {
      mbar_init(sb + OFF_FULL(s), 1);
      mbar_init(sb + OFF_EMPTY(s), NWC);
    }
    asm volatile("fence.proxy.async.shared::cta;" ::: "memory");
  }
  if (tid < 32) {
    reinterpret_cast<uint32_t*>(smem + OFF_LIVE)[tid] =
        reinterpret_cast<const uint32_t*>(g_live)[blockIdx.x * 32 + tid];
  }
  __syncthreads();

  const unsigned char* lv = reinterpret_cast<const unsigned char*>(smem + OFF_LIVE);

  if (w == NWC) {
    // -------- producer warp --------
    if (lane == 0) {
      for (int kb = 0; kb < NKITER; kb++) {
        const int st = kb & (NSTAGES - 1);
        if (kb >= NSTAGES) mbar_wait(sb + OFF_EMPTY(st), ((kb - NSTAGES) >> 2) & 1);
        const unsigned L = lv[kb];
        const uint32_t tx = (L ? A_BYTES : 0u) + (uint32_t)__popc(L) * BBLK_BYTES;
        mbar_expect_tx(sb + OFF_FULL(st), tx);
        const uint32_t dst = sb + SMEM_DATA0 + st * STAGE_BYTES;
        if (L) tma_load_2d(dst, &tmA, kb * KT, m0, sb + OFF_FULL(st));
        #pragma unroll
        for (int j = 0; j < 8; j++)
          if ((L >> j) & 1)
            tma_load_2d(dst + A_BYTES + j * BBLK_BYTES, &tmB, kb * KT,
                        n0 + j * 32, sb + OFF_FULL(st));
      }
    }
    return;
  }

  // -------- compute warps --------
  const int wm_ = (w >> 2) * 64;     // warp m offset
  const int wn_ = (w & 3) * 64;      // warp n offset
  const int j0  = wn_ >> 5;          // first of the warp's two n-blocks

  uint32_t arow[4], brow[8];
  #pragma unroll
  for (int mt = 0; mt < 4; mt++) arow[mt] = (wm_ + mt * 16 + grp) * 128;
  #pragma unroll
  for (int nt = 0; nt < 8; nt++)
    brow[nt] = (uint32_t)(((wn_ + nt * 8) >> 5) * BBLK_BYTES +
                          ((nt & 3) * 8 + grp) * 128);
  const uint32_t xorb = ((uint32_t)(c4 << 3)) ^ ((uint32_t)(grp << 4));

  float acc[4][8][4];
  #pragma unroll
  for (int mt = 0; mt < 4; mt++)
    #pragma unroll
    for (int nt = 0; nt < 8; nt++)
      #pragma unroll
      for (int r = 0; r < 4; r++) acc[mt][nt][r] = 0.f;

  for (int kb = 0; kb < NKITER; kb++) {
    const int st = kb & (NSTAGES - 1);
    mbar_wait(sb + OFF_FULL(st), (kb >> 2) & 1);
    const unsigned L = lv[kb];
    const bool l0 = (L >> j0) & 1;
    const bool l1 = (L >> (j0 + 1)) & 1;
    const char* As = smem + SMEM_DATA0 + st * STAGE_BYTES;
    const char* Bs = As + A_BYTES;
    if (l0 & l1)      stage_mma<true, true >(As, Bs, arow, brow, xorb, acc);
    else if (l0)      stage_mma<true, false>(As, Bs, arow, brow, xorb, acc);
    else if (l1)      stage_mma<false, true>(As, Bs, arow, brow, xorb, acc);
    if (lane == 0) mbar_arrive(sb + OFF_EMPTY(st));
  }

  // -------- epilogue --------
  #pragma unroll
  for (int nt = 0; nt < 8; nt++) {
    const int col = n0 + wn_ + nt * 8 + c4 * 2;
    const float2 bv = *reinterpret_cast<const float2*>(bias + col);
    #pragma unroll
    for (int mt = 0; mt < 4; mt++) {
      const int row = m0 + wm_ + mt * 16 + grp;
      float2 o0, o1;
      o0.x = acc[mt][nt][0] + bv.x;
      o0.y = acc[mt][nt][1] + bv.y;
      o1.x = acc[mt][nt][2] + bv.x;
      o1.y = acc[mt][nt][3] + bv.y;
      *reinterpret_cast<float2*>(out + (size_t)row * NDIM + col) = o0;
      *reinterpret_cast<float2*>(out + (size_t)(row + 8) * NDIM + col) = o1;
    }
  }
}

// ---------------- host launch ----------------

typedef CUresult (*EncodeTiledFn)(
    CUtensorMap*, CUtensorMapDataType, cuuint32_t, void*, const cuuint64_t*,
    const cuuint64_t*, const cuuint32_t*, const cuuint32_t*,
    CUtensorMapInterleave, CUtensorMapSwizzle, CUtensorMapL2promotion,
    CUtensorMapFloatOOBfill);

extern "C" void kernel_launch(void* const* d_in, const int* in_sizes, int n_in,
                              void* d_out, int out_size) {
  const float* x = nullptr;
  const float* wgt = nullptr;
  const float* bias = nullptr;
  const int* bm = nullptr;
  for (int i = 0; i < n_in; i++) {
    long long sz = in_sizes[i];
    if (sz == (long long)MDIM * KDIM)       x    = (const float*)d_in[i];
    else if (sz == (long long)NDIM * KDIM)  wgt  = (const float*)d_in[i];
    else if (sz == NDIM)                    bias = (const float*)d_in[i];
    else if (sz == (NDIM / BLK) * (KDIM / BLK)) bm = (const int*)d_in[i];
  }

  void* wm_ptr = nullptr;
  void* xt_ptr = nullptr;
  void* lv_ptr = nullptr;
  cudaGetSymbolAddress(&wm_ptr, g_wm);
  cudaGetSymbolAddress(&xt_ptr, g_xt);
  cudaGetSymbolAddress(&lv_ptr, g_live);

  // 1) Pre-pass
  premask_kernel<<<(NDIM * KDIM / 8) / 256, 256>>>(
      (const float4*)wgt, bm, (float*)wm_ptr);
  cvtx_kernel<<<(int)(((size_t)MDIM * KDIM / 8) / 256), 256>>>(
      (const float4*)x, (float*)xt_ptr);
  livemask_kernel<<<8, 256>>>(bm, (unsigned char*)lv_ptr);

  // 2) TMA descriptors
  EncodeTiledFn enc = nullptr;
  cudaDriverEntryPointQueryResult qr;
  cudaGetDriverEntryPoint("cuTensorMapEncodeTiled", (void**)&enc,
                          cudaEnableDefault, &qr);

  CUtensorMap tmA, tmB;
  {
    cuuint64_t dims[2]    = {(cuuint64_t)KDIM, (cuuint64_t)MDIM};
    cuuint64_t strides[1] = {(cuuint64_t)KDIM * sizeof(float)};
    cuuint32_t box[2]     = {KT, TM};
    cuuint32_t es[2]      = {1, 1};
    enc(&tmA, CU_TENSOR_MAP_DATA_TYPE_FLOAT32, 2, xt_ptr, dims, strides, box,
        es, CU_TENSOR_MAP_INTERLEAVE_NONE, CU_TENSOR_MAP_SWIZZLE_128B,
        CU_TENSOR_MAP_L2_PROMOTION_L2_128B, CU_TENSOR_MAP_FLOAT_OOB_FILL_NONE);
  }
  {
    cuuint64_t dims[2]    = {(cuuint64_t)KDIM, (cuuint64_t)NDIM};
    cuuint64_t strides[1] = {(cuuint64_t)KDIM * sizeof(float)};
    cuuint32_t box[2]     = {KT, 32};    // one 32x32 n-block per TMA
    cuuint32_t es[2]      = {1, 1};
    enc(&tmB, CU_TENSOR_MAP_DATA_TYPE_FLOAT32, 2, wm_ptr, dims, strides, box,
        es, CU_TENSOR_MAP_INTERLEAVE_NONE, CU_TENSOR_MAP_SWIZZLE_128B,
        CU_TENSOR_MAP_L2_PROMOTION_L2_128B, CU_TENSOR_MAP_FLOAT_OOB_FILL_NONE);
  }

  // 3) GEMM: grid.x = n-tiles (16), grid.y = m-tiles (64)
  cudaFuncSetAttribute(bsl_gemm_kernel,
                       cudaFuncAttributeMaxDynamicSharedMemorySize, SMEM_TOTAL);
  dim3 grid(NDIM / TN, MDIM / TM);
  bsl_gemm_kernel<<<grid, THREADS, SMEM_TOTAL>>>(tmA, tmB, bias, (float*)d_out);
}

// round 4
// speedup vs baseline: 1.1946x; 1.0141x over previous
#include <cuda_runtime.h>
#include <cuda.h>
#include <cstdint>
#include <cstddef>

// Problem dims
#define MDIM 8192
#define NDIM 4096
#define KDIM 4096
#define BLK  32

// GEMM tiling
#define TM 128
#define TN 256
#define KT 32                 // fp32 elements per K-chunk = one K-block = 128B row
#define NSTAGES 4
#define NKITER (KDIM / KT)    // 128
#define NWC 8                 // compute warps
#define THREADS 288           // 8 compute warps + 1 producer warp

#define A_BYTES (TM * KT * 4)         // 16384
#define B_BYTES (TN * KT * 4)         // 32768
#define BBLK_BYTES (32 * KT * 4)      // 4096 per n-block
#define STAGE_BYTES (A_BYTES + B_BYTES)               // 49152
#define SMEM_DATA0 1024
#define SMEM_TOTAL (SMEM_DATA0 + NSTAGES * STAGE_BYTES)  // 197632

#define OFF_FULL(s)  (16 + (s) * 8)
#define OFF_EMPTY(s) (64 + (s) * 8)
#define OFF_LIVE     512              // 128 bytes: live mask per k-block

// Scratch (static device globals: allowed, no runtime alloc)
__device__ float g_wm[(size_t)NDIM * (size_t)KDIM];   // masked+tf32+permuted W
__device__ float g_xt[(size_t)MDIM * (size_t)KDIM];   // tf32+permuted x
__device__ unsigned char g_live[(NDIM / TN) * NKITER];  // [16][128]

// ---------------- device helpers ----------------

__device__ __forceinline__ uint32_t smem_u32(const void* p) {
  uint32_t r;
  asm("{ .reg .u64 t; cvta.to.shared.u64 t, %1; cvt.u32.u64 %0, t; }"
      : "=r"(r) : "l"(p));
  return r;
}
__device__ __forceinline__ void mbar_init(uint32_t a, uint32_t cnt) {
  asm volatile("mbarrier.init.shared::cta.b64 [%0], %1;"
               :: "r"(a), "r"(cnt) : "memory");
}
__device__ __forceinline__ void mbar_expect_tx(uint32_t a, uint32_t bytes) {
  asm volatile("mbarrier.arrive.expect_tx.shared::cta.b64 _, [%0], %1;"
               :: "r"(a), "r"(bytes) : "memory");
}
__device__ __forceinline__ void mbar_arrive(uint32_t a) {
  asm volatile("mbarrier.arrive.shared::cta.b64 _, [%0];"
               :: "r"(a) : "memory");
}
__device__ __forceinline__ void mbar_wait(uint32_t a, uint32_t parity) {
  asm volatile(
      "{\n\t.reg .pred P;\n\t"
      "WL%=:\n\t"
      "mbarrier.try_wait.parity.acquire.cta.shared::cta.b64 P, [%0], %1, 0x989680;\n\t"
      "@P bra WD%=;\n\t"
      "bra WL%=;\n\t"
      "WD%=:\n\t}"
      :: "r"(a), "r"(parity) : "memory");
}
__device__ __forceinline__ void tma_load_2d(uint32_t smem_dst, const void* map,
                                            int cx, int cy, uint32_t bar) {
  asm volatile(
      "cp.async.bulk.tensor.2d.shared::cta.global.tile.mbarrier::complete_tx::bytes "
      "[%0], [%1, {%2, %3}], [%4];"
      :: "r"(smem_dst), "l"(map), "r"(cx), "r"(cy), "r"(bar) : "memory");
}
__device__ __forceinline__ uint32_t f2tf32(float f) {
  uint32_t u;
  asm("cvt.rna.tf32.f32 %0, %1;" : "=r"(u) : "f"(f));
  return u;
}
__device__ __forceinline__ void mma_tf32(float* c, uint32_t a0, uint32_t a1,
                                         uint32_t a2, uint32_t a3,
                                         uint32_t b0, uint32_t b1) {
  asm volatile(
      "mma.sync.aligned.m16n8k8.row.col.f32.tf32.tf32.f32 "
      "{%0,%1,%2,%3}, {%4,%5,%6,%7}, {%8,%9}, {%0,%1,%2,%3};"
      : "+f"(c[0]), "+f"(c[1]), "+f"(c[2]), "+f"(c[3])
      : "r"(a0), "r"(a1), "r"(a2), "r"(a3), "r"(b0), "r"(b1));
}

// ---------------- column permutation ----------------
// Within each 32-col k-block (one 128B SMEM row), logical col c (ks=c>>3,
// j=c&7, c4=j&3, h=j>>2) is stored at byte offset:
//   off = (c4&1)*8 + ks*16 + (c4>>1)*64 + h*4
// Pair (c4, c4+4) is an aligned 8B LDS.64. c4 occupies bits {3,6}, ks bits
// {4,5}; the SW128 swizzle XOR (grp*16, bits {4,5,6}) therefore never maps two
// half-warp lanes to the same bank slot -> provably conflict-free LDS.64.
// (Round-3 layout put c4 in bits {3,4}, colliding with grp bit 4 -> 2-way
//  conflict on every fragment load; that was the 68.8% L1 SOL.)

__device__ __forceinline__ int perm_src_col(int p) {
  // inverse map: stored slot p (0..31) <- logical col
  int h  = p & 1;
  int c4 = ((p >> 1) & 1) | (((p >> 4) & 1) << 1);
  int ks = (p >> 2) & 3;
  return ks * 8 + c4 + 4 * h;
}

// ---------------- pre-pass kernels ----------------

// W: mask + tf32-round + permute. One thread per 32-col k-block (128B).
__global__ void __launch_bounds__(256)
premask_kernel(const float4* __restrict__ w, const int* __restrict__ bm,
               float* __restrict__ wm) {
  int t = blockIdx.x * 256 + threadIdx.x;     // block index over [NDIM][KDIM/32]
  int o  = t >> 7;                             // output row
  int kb = t & 127;                            // k-block
  uint4* dst = reinterpret_cast<uint4*>(wm) + (size_t)t * 8;
  if (bm[((o >> 5) << 7) + kb] == 0) {
    uint4 z = make_uint4(0u, 0u, 0u, 0u);
    #pragma unroll
    for (int q = 0; q < 8; q++) dst[q] = z;
    return;
  }
  const float4* src = w + (size_t)t * 8;
  float v[32];
  #pragma unroll
  for (int q = 0; q < 8; q++) {
    float4 f = src[q];
    v[q * 4 + 0] = f.x; v[q * 4 + 1] = f.y; v[q * 4 + 2] = f.z; v[q * 4 + 3] = f.w;
  }
  uint32_t ov[32];
  #pragma unroll
  for (int p = 0; p < 32; p++) ov[p] = f2tf32(v[perm_src_col(p)]);
  #pragma unroll
  for (int q = 0; q < 8; q++)
    dst[q] = make_uint4(ov[q * 4], ov[q * 4 + 1], ov[q * 4 + 2], ov[q * 4 + 3]);
}

// x: tf32-round + permute.
__global__ void __launch_bounds__(256)
cvtx_kernel(const float4* __restrict__ x, float* __restrict__ xt) {
  int t = blockIdx.x * 256 + threadIdx.x;
  const float4* src = x + (size_t)t * 8;
  uint4* dst = reinterpret_cast<uint4*>(xt) + (size_t)t * 8;
  float v[32];
  #pragma unroll
  for (int q = 0; q < 8; q++) {
    float4 f = src[q];
    v[q * 4 + 0] = f.x; v[q * 4 + 1] = f.y; v[q * 4 + 2] = f.z; v[q * 4 + 3] = f.w;
  }
  uint32_t ov[32];
  #pragma unroll
  for (int p = 0; p < 32; p++) ov[p] = f2tf32(v[perm_src_col(p)]);
  #pragma unroll
  for (int q = 0; q < 8; q++)
    dst[q] = make_uint4(ov[q * 4], ov[q * 4 + 1], ov[q * 4 + 2], ov[q * 4 + 3]);
}

// Live mask: per (n-tile cn, k-block kb), bit j = block (cn*8+j, kb) nonzero.
__global__ void __launch_bounds__(256)
livemask_kernel(const int* __restrict__ bm, unsigned char* __restrict__ lv) {
  int t = blockIdx.x * 256 + threadIdx.x;   // 0..2047
  int cn = t >> 7, kb = t & 127;
  unsigned b = 0;
  #pragma unroll
  for (int j = 0; j < 8; j++)
    b |= (bm[(cn * 8 + j) * 128 + kb] ? 1u : 0u) << j;
  lv[t] = (unsigned char)b;
}

// ---------------- GEMM ----------------
// CTA 128x256, 8 compute warps (2x4 grid of 64x64 warp tiles) + 1 producer.
// tf32 mma.sync m16n8k8; TMA+mbarrier 4-stage pipeline; per-n-block B loads
// with sparsity skipping; conflict-free LDS.64 fragment loads.

template <bool L0, bool L1>
__device__ __forceinline__ void stage_mma(const char* As, const char* Bs,
                                          const uint32_t* arow,
                                          const uint32_t* brow,
                                          uint32_t xorb,
                                          float acc[4][8][4]) {
  #pragma unroll
  for (int ks = 0; ks < 4; ks++) {
    const uint32_t cx = ((uint32_t)(ks << 4)) ^ xorb;
    uint2 p0[4], p1[4];
    #pragma unroll
    for (int mt = 0; mt < 4; mt++) {
      p0[mt] = *reinterpret_cast<const uint2*>(As + arow[mt] + cx);
      p1[mt] = *reinterpret_cast<const uint2*>(As + arow[mt] + 1024 + cx);
    }
    if (L0) {
      uint2 b[4];
      #pragma unroll
      for (int nt = 0; nt < 4; nt++)
        b[nt] = *reinterpret_cast<const uint2*>(Bs + brow[nt] + cx);
      #pragma unroll
      for (int mt = 0; mt < 4; mt++)
        #pragma unroll
        for (int nt = 0; nt < 4; nt++)
          mma_tf32(acc[mt][nt], p0[mt].x, p1[mt].x, p0[mt].y, p1[mt].y,
                   b[nt].x, b[nt].y);
    }
    if (L1) {
      uint2 b[4];
      #pragma unroll
      for (int nt = 0; nt < 4; nt++)
        b[nt] = *reinterpret_cast<const uint2*>(Bs + brow[nt + 4] + cx);
      #pragma unroll
      for (int mt = 0; mt < 4; mt++)
        #pragma unroll
        for (int nt = 0; nt < 4; nt++)
          mma_tf32(acc[mt][nt + 4], p0[mt].x, p1[mt].x, p0[mt].y, p1[mt].y,
                   b[nt].x, b[nt].y);
    }
  }
}

__global__ void __launch_bounds__(THREADS, 1)
bsl_gemm_kernel(const __grid_constant__ CUtensorMap tmA,
                const __grid_constant__ CUtensorMap tmB,
                const float* __restrict__ bias,
                float* __restrict__ out) {
  extern __shared__ char smem[];
  const uint32_t sb = smem_u32(smem);
  const int tid  = threadIdx.x;
  const int w    = tid >> 5;
  const int lane = tid & 31;
  const int grp  = lane >> 2;
  const int c4   = lane & 3;

  // grid: x = n-tile (16), y = m-tile (64)  -> wave-blocked for L2 reuse
  const int n0 = blockIdx.x * TN;
  const int m0 = blockIdx.y * TM;

  if (tid == 0) {
    #pragma unroll
    for (int s = 0; s < NSTAGES; s++) {
      mbar_init(sb + OFF_FULL(s), 1);
      mbar_init(sb + OFF_EMPTY(s), NWC);
    }
    asm volatile("fence.proxy.async.shared::cta;" ::: "memory");
  }
  if (tid < 32) {
    reinterpret_cast<uint32_t*>(smem + OFF_LIVE)[tid] =
        reinterpret_cast<const uint32_t*>(g_live)[blockIdx.x * 32 + tid];
  }
  __syncthreads();

  const unsigned char* lv = reinterpret_cast<const unsigned char*>(smem + OFF_LIVE);

  if (w == NWC) {
    // -------- producer warp --------
    if (lane == 0) {
      for (int kb = 0; kb < NKITER; kb++) {
        const int st = kb & (NSTAGES - 1);
        if (kb >= NSTAGES) mbar_wait(sb + OFF_EMPTY(st), ((kb - NSTAGES) >> 2) & 1);
        const unsigned L = lv[kb];
        const uint32_t tx = (L ? A_BYTES : 0u) + (uint32_t)__popc(L) * BBLK_BYTES;
        mbar_expect_tx(sb + OFF_FULL(st), tx);
        const uint32_t dst = sb + SMEM_DATA0 + st * STAGE_BYTES;
        if (L) tma_load_2d(dst, &tmA, kb * KT, m0, sb + OFF_FULL(st));
        #pragma unroll
        for (int j = 0; j < 8; j++)
          if ((L >> j) & 1)
            tma_load_2d(dst + A_BYTES + j * BBLK_BYTES, &tmB, kb * KT,
                        n0 + j * 32, sb + OFF_FULL(st));
      }
    }
    return;
  }

  // -------- compute warps --------
  const int wm_ = (w >> 2) * 64;     // warp m offset
  const int wn_ = (w & 3) * 64;      // warp n offset
  const int j0  = wn_ >> 5;          // first of the warp's two n-blocks

  uint32_t arow[4], brow[8];
  #pragma unroll
  for (int mt = 0; mt < 4; mt++) arow[mt] = (wm_ + mt * 16 + grp) * 128;
  #pragma unroll
  for (int nt = 0; nt < 8; nt++)
    brow[nt] = (uint32_t)(((wn_ + nt * 8) >> 5) * BBLK_BYTES +
                          ((nt & 3) * 8 + grp) * 128);
  // c4 -> bits {3,6}; swizzle XOR grp -> bits {4,5,6}; ks added as bits {4,5}.
  const uint32_t xorb =
      (((uint32_t)(c4 & 1) << 3) | ((uint32_t)(c4 >> 1) << 6)) ^
      ((uint32_t)grp << 4);

  float acc[4][8][4];
  #pragma unroll
  for (int mt = 0; mt < 4; mt++)
    #pragma unroll
    for (int nt = 0; nt < 8; nt++)
      #pragma unroll
      for (int r = 0; r < 4; r++) acc[mt][nt][r] = 0.f;

  for (int kb = 0; kb < NKITER; kb++) {
    const int st = kb & (NSTAGES - 1);
    mbar_wait(sb + OFF_FULL(st), (kb >> 2) & 1);
    const unsigned L = lv[kb];
    const bool l0 = (L >> j0) & 1;
    const bool l1 = (L >> (j0 + 1)) & 1;
    const char* As = smem + SMEM_DATA0 + st * STAGE_BYTES;
    const char* Bs = As + A_BYTES;
    if (l0 & l1)      stage_mma<true, true >(As, Bs, arow, brow, xorb, acc);
    else if (l0)      stage_mma<true, false>(As, Bs, arow, brow, xorb, acc);
    else if (l1)      stage_mma<false, true>(As, Bs, arow, brow, xorb, acc);
    if (lane == 0) mbar_arrive(sb + OFF_EMPTY(st));
  }

  // -------- epilogue --------
  #pragma unroll
  for (int nt = 0; nt < 8; nt++) {
    const int col = n0 + wn_ + nt * 8 + c4 * 2;
    const float2 bv = *reinterpret_cast<const float2*>(bias + col);
    #pragma unroll
    for (int mt = 0; mt < 4; mt++) {
      const int row = m0 + wm_ + mt * 16 + grp;
      float2 o0, o1;
      o0.x = acc[mt][nt][0] + bv.x;
      o0.y = acc[mt][nt][1] + bv.y;
      o1.x = acc[mt][nt][2] + bv.x;
      o1.y = acc[mt][nt][3] + bv.y;
      *reinterpret_cast<float2*>(out + (size_t)row * NDIM + col) = o0;
      *reinterpret_cast<float2*>(out + (size_t)(row + 8) * NDIM + col) = o1;
    }
  }
}

// ---------------- host launch ----------------

typedef CUresult (*EncodeTiledFn)(
    CUtensorMap*, CUtensorMapDataType, cuuint32_t, void*, const cuuint64_t*,
    const cuuint64_t*, const cuuint32_t*, const cuuint32_t*,
    CUtensorMapInterleave, CUtensorMapSwizzle, CUtensorMapL2promotion,
    CUtensorMapFloatOOBfill);

extern "C" void kernel_launch(void* const* d_in, const int* in_sizes, int n_in,
                              void* d_out, int out_size) {
  const float* x = nullptr;
  const float* wgt = nullptr;
  const float* bias = nullptr;
  const int* bm = nullptr;
  for (int i = 0; i < n_in; i++) {
    long long sz = in_sizes[i];
    if (sz == (long long)MDIM * KDIM)       x    = (const float*)d_in[i];
    else if (sz == (long long)NDIM * KDIM)  wgt  = (const float*)d_in[i];
    else if (sz == NDIM)                    bias = (const float*)d_in[i];
    else if (sz == (NDIM / BLK) * (KDIM / BLK)) bm = (const int*)d_in[i];
  }

  void* wm_ptr = nullptr;
  void* xt_ptr = nullptr;
  void* lv_ptr = nullptr;
  cudaGetSymbolAddress(&wm_ptr, g_wm);
  cudaGetSymbolAddress(&xt_ptr, g_xt);
  cudaGetSymbolAddress(&lv_ptr, g_live);

  // 1) Pre-pass (one thread per 32-col k-block)
  premask_kernel<<<(NDIM * (KDIM / 32)) / 256, 256>>>(
      (const float4*)wgt, bm, (float*)wm_ptr);
  cvtx_kernel<<<(int)(((size_t)MDIM * (KDIM / 32)) / 256), 256>>>(
      (const float4*)x, (float*)xt_ptr);
  livemask_kernel<<<8, 256>>>(bm, (unsigned char*)lv_ptr);

  // 2) TMA descriptors
  EncodeTiledFn enc = nullptr;
  cudaDriverEntryPointQueryResult qr;
  cudaGetDriverEntryPoint("cuTensorMapEncodeTiled", (void**)&enc,
                          cudaEnableDefault, &qr);

  CUtensorMap tmA, tmB;
  {
    cuuint64_t dims[2]    = {(cuuint64_t)KDIM, (cuuint64_t)MDIM};
    cuuint64_t strides[1] = {(cuuint64_t)KDIM * sizeof(float)};
    cuuint32_t box[2]     = {KT, TM};
    cuuint32_t es[2]      = {1, 1};
    enc(&tmA, CU_TENSOR_MAP_DATA_TYPE_FLOAT32, 2, xt_ptr, dims, strides, box,
        es, CU_TENSOR_MAP_INTERLEAVE_NONE, CU_TENSOR_MAP_SWIZZLE_128B,
        CU_TENSOR_MAP_L2_PROMOTION_L2_128B, CU_TENSOR_MAP_FLOAT_OOB_FILL_NONE);
  }
  {
    cuuint64_t dims[2]    = {(cuuint64_t)KDIM, (cuuint64_t)NDIM};
    cuuint64_t strides[1] = {(cuuint64_t)KDIM * sizeof(float)};
    cuuint32_t box[2]     = {KT, 32};    // one 32x32 n-block per TMA
    cuuint32_t es[2]      = {1, 1};
    enc(&tmB, CU_TENSOR_MAP_DATA_TYPE_FLOAT32, 2, wm_ptr, dims, strides, box,
        es, CU_TENSOR_MAP_INTERLEAVE_NONE, CU_TENSOR_MAP_SWIZZLE_128B,
        CU_TENSOR_MAP_L2_PROMOTION_L2_128B, CU_TENSOR_MAP_FLOAT_OOB_FILL_NONE);
  }

  // 3) GEMM: grid.x = n-tiles (16), grid.y = m-tiles (64)
  cudaFuncSetAttribute(bsl_gemm_kernel,
                       cudaFuncAttributeMaxDynamicSharedMemorySize, SMEM_TOTAL);
  dim3 grid(NDIM / TN, MDIM / TM);
  bsl_gemm_kernel<<<grid, THREADS, SMEM_TOTAL>>>(tmA, tmB, bias, (float*)d_out);
}

// round 5
// speedup vs baseline: 1.2965x; 1.0853x over previous
#include <cuda_runtime.h>
#include <cuda.h>
#include <cstdint>
#include <cstddef>

// Problem dims
#define MDIM 8192
#define NDIM 4096
#define KDIM 4096
#define BLK  32

// GEMM tiling
#define TM 128
#define TN 256
#define KT 32                 // fp32 elements per K-chunk = one K-block = 128B row
#define NSTAGES 4
#define NKITER (KDIM / KT)    // 128
#define NWC 16                // compute warps (2m x 8n, warp tile 64x32)
#define THREADS 544           // 16 compute warps + 1 producer warp

#define A_BYTES (TM * KT * 4)         // 16384
#define B_BYTES (TN * KT * 4)         // 32768
#define BBLK_BYTES (32 * KT * 4)      // 4096 per n-block
#define STAGE_BYTES (A_BYTES + B_BYTES)               // 49152
#define SMEM_DATA0 1024
#define SMEM_TOTAL (SMEM_DATA0 + NSTAGES * STAGE_BYTES)  // 197632

#define OFF_FULL(s)  (16 + (s) * 8)
#define OFF_EMPTY(s) (64 + (s) * 8)
#define OFF_LIVE     512              // 128 bytes: live mask per k-block

// Scratch (static device globals: allowed, no runtime alloc)
__device__ float g_wm[(size_t)NDIM * (size_t)KDIM];   // masked+tf32+permuted W
__device__ float g_xt[(size_t)MDIM * (size_t)KDIM];   // tf32+permuted x
__device__ unsigned char g_live[(NDIM / TN) * NKITER];  // [16][128]

// ---------------- device helpers ----------------

__device__ __forceinline__ uint32_t smem_u32(const void* p) {
  uint32_t r;
  asm("{ .reg .u64 t; cvta.to.shared.u64 t, %1; cvt.u32.u64 %0, t; }"
      : "=r"(r) : "l"(p));
  return r;
}
__device__ __forceinline__ void mbar_init(uint32_t a, uint32_t cnt) {
  asm volatile("mbarrier.init.shared::cta.b64 [%0], %1;"
               :: "r"(a), "r"(cnt) : "memory");
}
__device__ __forceinline__ void mbar_expect_tx(uint32_t a, uint32_t bytes) {
  asm volatile("mbarrier.arrive.expect_tx.shared::cta.b64 _, [%0], %1;"
               :: "r"(a), "r"(bytes) : "memory");
}
__device__ __forceinline__ void mbar_arrive(uint32_t a) {
  asm volatile("mbarrier.arrive.shared::cta.b64 _, [%0];"
               :: "r"(a) : "memory");
}
__device__ __forceinline__ void mbar_wait(uint32_t a, uint32_t parity) {
  asm volatile(
      "{\n\t.reg .pred P;\n\t"
      "WL%=:\n\t"
      "mbarrier.try_wait.parity.acquire.cta.shared::cta.b64 P, [%0], %1, 0x989680;\n\t"
      "@P bra WD%=;\n\t"
      "bra WL%=;\n\t"
      "WD%=:\n\t}"
      :: "r"(a), "r"(parity) : "memory");
}
__device__ __forceinline__ void tma_load_2d(uint32_t smem_dst, const void* map,
                                            int cx, int cy, uint32_t bar) {
  asm volatile(
      "cp.async.bulk.tensor.2d.shared::cta.global.tile.mbarrier::complete_tx::bytes "
      "[%0], [%1, {%2, %3}], [%4];"
      :: "r"(smem_dst), "l"(map), "r"(cx), "r"(cy), "r"(bar) : "memory");
}
__device__ __forceinline__ uint32_t f2tf32(float f) {
  uint32_t u;
  asm("cvt.rna.tf32.f32 %0, %1;" : "=r"(u) : "f"(f));
  return u;
}
__device__ __forceinline__ void mma_tf32(float* c, uint32_t a0, uint32_t a1,
                                         uint32_t a2, uint32_t a3,
                                         uint32_t b0, uint32_t b1) {
  asm volatile(
      "mma.sync.aligned.m16n8k8.row.col.f32.tf32.tf32.f32 "
      "{%0,%1,%2,%3}, {%4,%5,%6,%7}, {%8,%9}, {%0,%1,%2,%3};"
      : "+f"(c[0]), "+f"(c[1]), "+f"(c[2]), "+f"(c[3])
      : "r"(a0), "r"(a1), "r"(a2), "r"(a3), "r"(b0), "r"(b1));
}

// ---------------- column permutation ----------------
// Within each 32-col k-block (one 128B SMEM row), logical col c (ks=c>>3,
// j=c&7, c4=j&3, h=j>>2) is stored at byte offset:
//   off = (c4&1)*8 + ks*16 + (c4>>1)*64 + h*4
// Pair (c4, c4+4) is an aligned 8B LDS.64. c4 occupies bits {3,6}, ks bits
// {4,5}; the SW128 swizzle XOR (grp*16, bits {4,5,6}) never maps two half-warp
// lanes to the same bank slot -> conflict-free LDS.64 (verified R4: L1 69->43%).

__device__ __forceinline__ int perm_src_col(int p) {
  // inverse map: stored slot p (0..31) <- logical col
  int h  = p & 1;
  int c4 = ((p >> 1) & 1) | (((p >> 4) & 1) << 1);
  int ks = (p >> 2) & 3;
  return ks * 8 + c4 + 4 * h;
}

// ---------------- pre-pass kernels ----------------

// W: mask + tf32-round + permute. One thread per 32-col k-block (128B).
__global__ void __launch_bounds__(256)
premask_kernel(const float4* __restrict__ w, const int* __restrict__ bm,
               float* __restrict__ wm) {
  int t = blockIdx.x * 256 + threadIdx.x;     // block index over [NDIM][KDIM/32]
  int o  = t >> 7;                             // output row
  int kb = t & 127;                            // k-block
  uint4* dst = reinterpret_cast<uint4*>(wm) + (size_t)t * 8;
  if (bm[((o >> 5) << 7) + kb] == 0) {
    uint4 z = make_uint4(0u, 0u, 0u, 0u);
    #pragma unroll
    for (int q = 0; q < 8; q++) dst[q] = z;
    return;
  }
  const float4* src = w + (size_t)t * 8;
  float v[32];
  #pragma unroll
  for (int q = 0; q < 8; q++) {
    float4 f = src[q];
    v[q * 4 + 0] = f.x; v[q * 4 + 1] = f.y; v[q * 4 + 2] = f.z; v[q * 4 + 3] = f.w;
  }
  uint32_t ov[32];
  #pragma unroll
  for (int p = 0; p < 32; p++) ov[p] = f2tf32(v[perm_src_col(p)]);
  #pragma unroll
  for (int q = 0; q < 8; q++)
    dst[q] = make_uint4(ov[q * 4], ov[q * 4 + 1], ov[q * 4 + 2], ov[q * 4 + 3]);
}

// x: tf32-round + permute.
__global__ void __launch_bounds__(256)
cvtx_kernel(const float4* __restrict__ x, float* __restrict__ xt) {
  int t = blockIdx.x * 256 + threadIdx.x;
  const float4* src = x + (size_t)t * 8;
  uint4* dst = reinterpret_cast<uint4*>(xt) + (size_t)t * 8;
  float v[32];
  #pragma unroll
  for (int q = 0; q < 8; q++) {
    float4 f = src[q];
    v[q * 4 + 0] = f.x; v[q * 4 + 1] = f.y; v[q * 4 + 2] = f.z; v[q * 4 + 3] = f.w;
  }
  uint32_t ov[32];
  #pragma unroll
  for (int p = 0; p < 32; p++) ov[p] = f2tf32(v[perm_src_col(p)]);
  #pragma unroll
  for (int q = 0; q < 8; q++)
    dst[q] = make_uint4(ov[q * 4], ov[q * 4 + 1], ov[q * 4 + 2], ov[q * 4 + 3]);
}

// Live mask: per (n-tile cn, k-block kb), bit j = block (cn*8+j, kb) nonzero.
__global__ void __launch_bounds__(256)
livemask_kernel(const int* __restrict__ bm, unsigned char* __restrict__ lv) {
  int t = blockIdx.x * 256 + threadIdx.x;   // 0..2047
  int cn = t >> 7, kb = t & 127;
  unsigned b = 0;
  #pragma unroll
  for (int j = 0; j < 8; j++)
    b |= (bm[(cn * 8 + j) * 128 + kb] ? 1u : 0u) << j;
  lv[t] = (unsigned char)b;
}

// ---------------- GEMM ----------------
// CTA 128x256, 16 compute warps (2m x 8n grid of 64x32 warp tiles) + 1
// producer. Each compute warp owns exactly one 32-wide n-block -> whole-warp
// sparsity skip (A loads, B loads and MMAs all gated). 17 warps/SM fills the
// latency gap that capped tensor at 49% with 9 warps.

__device__ __forceinline__ void stage_mma(const char* As, const char* Bs,
                                          const uint32_t* arow,
                                          const uint32_t* brow,
                                          uint32_t xorb,
                                          float acc[4][4][4]) {
  #pragma unroll
  for (int ks = 0; ks < 4; ks++) {
    const uint32_t cx = ((uint32_t)(ks << 4)) ^ xorb;
    uint2 p0[4], p1[4];
    #pragma unroll
    for (int mt = 0; mt < 4; mt++) {
      p0[mt] = *reinterpret_cast<const uint2*>(As + arow[mt] + cx);
      p1[mt] = *reinterpret_cast<const uint2*>(As + arow[mt] + 1024 + cx);
    }
    uint2 b[4];
    #pragma unroll
    for (int nt = 0; nt < 4; nt++)
      b[nt] = *reinterpret_cast<const uint2*>(Bs + brow[nt] + cx);
    #pragma unroll
    for (int mt = 0; mt < 4; mt++)
      #pragma unroll
      for (int nt = 0; nt < 4; nt++)
        mma_tf32(acc[mt][nt], p0[mt].x, p1[mt].x, p0[mt].y, p1[mt].y,
                 b[nt].x, b[nt].y);
  }
}

__global__ void __launch_bounds__(THREADS, 1)
bsl_gemm_kernel(const __grid_constant__ CUtensorMap tmA,
                const __grid_constant__ CUtensorMap tmB,
                const float* __restrict__ bias,
                float* __restrict__ out) {
  extern __shared__ char smem[];
  const uint32_t sb = smem_u32(smem);
  const int tid  = threadIdx.x;
  const int w    = tid >> 5;
  const int lane = tid & 31;
  const int grp  = lane >> 2;
  const int c4   = lane & 31 & 3;

  // grid: x = n-tile (16), y = m-tile (64)  -> wave-blocked for L2 reuse
  const int n0 = blockIdx.x * TN;
  const int m0 = blockIdx.y * TM;

  if (tid == 0) {
    #pragma unroll
    for (int s = 0; s < NSTAGES; s++) {
      mbar_init(sb + OFF_FULL(s), 1);
      mbar_init(sb + OFF_EMPTY(s), NWC);
    }
    asm volatile("fence.proxy.async.shared::cta;" ::: "memory");
  }
  if (tid < 32) {
    reinterpret_cast<uint32_t*>(smem + OFF_LIVE)[tid] =
        reinterpret_cast<const uint32_t*>(g_live)[blockIdx.x * 32 + tid];
  }
  __syncthreads();

  const unsigned char* lv = reinterpret_cast<const unsigned char*>(smem + OFF_LIVE);

  if (w == NWC) {
    // -------- producer warp --------
    if (lane == 0) {
      for (int kb = 0; kb < NKITER; kb++) {
        const int st = kb & (NSTAGES - 1);
        if (kb >= NSTAGES) mbar_wait(sb + OFF_EMPTY(st), ((kb - NSTAGES) >> 2) & 1);
        const unsigned L = lv[kb];
        const uint32_t tx = (L ? A_BYTES : 0u) + (uint32_t)__popc(L) * BBLK_BYTES;
        mbar_expect_tx(sb + OFF_FULL(st), tx);
        const uint32_t dst = sb + SMEM_DATA0 + st * STAGE_BYTES;
        if (L) tma_load_2d(dst, &tmA, kb * KT, m0, sb + OFF_FULL(st));
        #pragma unroll
        for (int j = 0; j < 8; j++)
          if ((L >> j) & 1)
            tma_load_2d(dst + A_BYTES + j * BBLK_BYTES, &tmB, kb * KT,
                        n0 + j * 32, sb + OFF_FULL(st));
      }
    }
    return;
  }

  // -------- compute warps: 2m x 8n, warp tile 64x32 (one n-block) --------
  const int wm_ = (w >> 3) * 64;     // warp m offset (0 or 64)
  const int j0  = w & 7;             // the warp's n-block
  const int wn_ = j0 * 32;           // warp n offset

  uint32_t arow[4], brow[4];
  #pragma unroll
  for (int mt = 0; mt < 4; mt++) arow[mt] = (wm_ + mt * 16 + grp) * 128;
  #pragma unroll
  for (int nt = 0; nt < 4; nt++)
    brow[nt] = (uint32_t)(j0 * BBLK_BYTES + (nt * 8 + grp) * 128);
  // c4 -> bits {3,6}; swizzle XOR grp -> bits {4,5,6}; ks added as bits {4,5}.
  const uint32_t xorb =
      (((uint32_t)(c4 & 1) << 3) | ((uint32_t)(c4 >> 1) << 6)) ^
      ((uint32_t)grp << 4);

  float acc[4][4][4];
  #pragma unroll
  for (int mt = 0; mt < 4; mt++)
    #pragma unroll
    for (int nt = 0; nt < 4; nt++)
      #pragma unroll
      for (int r = 0; r < 4; r++) acc[mt][nt][r] = 0.f;

  for (int kb = 0; kb < NKITER; kb++) {
    const int st = kb & (NSTAGES - 1);
    mbar_wait(sb + OFF_FULL(st), (kb >> 2) & 1);
    if ((lv[kb] >> j0) & 1) {
      const char* As = smem + SMEM_DATA0 + st * STAGE_BYTES;
      const char* Bs = As + A_BYTES;
      stage_mma(As, Bs, arow, brow, xorb, acc);
    }
    if (lane == 0) mbar_arrive(sb + OFF_EMPTY(st));
  }

  // -------- epilogue --------
  #pragma unroll
  for (int nt = 0; nt < 4; nt++) {
    const int col = n0 + wn_ + nt * 8 + c4 * 2;
    const float2 bv = *reinterpret_cast<const float2*>(bias + col);
    #pragma unroll
    for (int mt = 0; mt < 4; mt++) {
      const int row = m0 + wm_ + mt * 16 + grp;
      float2 o0, o1;
      o0.x = acc[mt][nt][0] + bv.x;
      o0.y = acc[mt][nt][1] + bv.y;
      o1.x = acc[mt][nt][2] + bv.x;
      o1.y = acc[mt][nt][3] + bv.y;
      *reinterpret_cast<float2*>(out + (size_t)row * NDIM + col) = o0;
      *reinterpret_cast<float2*>(out + (size_t)(row + 8) * NDIM + col) = o1;
    }
  }
}

// ---------------- host launch ----------------

typedef CUresult (*EncodeTiledFn)(
    CUtensorMap*, CUtensorMapDataType, cuuint32_t, void*, const cuuint64_t*,
    const cuuint64_t*, const cuuint32_t*, const cuuint32_t*,
    CUtensorMapInterleave, CUtensorMapSwizzle, CUtensorMapL2promotion,
    CUtensorMapFloatOOBfill);

extern "C" void kernel_launch(void* const* d_in, const int* in_sizes, int n_in,
                              void* d_out, int out_size) {
  const float* x = nullptr;
  const float* wgt = nullptr;
  const float* bias = nullptr;
  const int* bm = nullptr;
  for (int i = 0; i < n_in; i++) {
    long long sz = in_sizes[i];
    if (sz == (long long)MDIM * KDIM)       x    = (const float*)d_in[i];
    else if (sz == (long long)NDIM * KDIM)  wgt  = (const float*)d_in[i];
    else if (sz == NDIM)                    bias = (const float*)d_in[i];
    else if (sz == (NDIM / BLK) * (KDIM / BLK)) bm = (const int*)d_in[i];
  }

  void* wm_ptr = nullptr;
  void* xt_ptr = nullptr;
  void* lv_ptr = nullptr;
  cudaGetSymbolAddress(&wm_ptr, g_wm);
  cudaGetSymbolAddress(&xt_ptr, g_xt);
  cudaGetSymbolAddress(&lv_ptr, g_live);

  // 1) Pre-pass (one thread per 32-col k-block)
  premask_kernel<<<(NDIM * (KDIM / 32)) / 256, 256>>>(
      (const float4*)wgt, bm, (float*)wm_ptr);
  cvtx_kernel<<<(int)(((size_t)MDIM * (KDIM / 32)) / 256), 256>>>(
      (const float4*)x, (float*)xt_ptr);
  livemask_kernel<<<8, 256>>>(bm, (unsigned char*)lv_ptr);

  // 2) TMA descriptors
  EncodeTiledFn enc = nullptr;
  cudaDriverEntryPointQueryResult qr;
  cudaGetDriverEntryPoint("cuTensorMapEncodeTiled", (void**)&enc,
                          cudaEnableDefault, &qr);

  CUtensorMap tmA, tmB;
  {
    cuuint64_t dims[2]    = {(cuuint64_t)KDIM, (cuuint64_t)MDIM};
    cuuint64_t strides[1] = {(cuuint64_t)KDIM * sizeof(float)};
    cuuint32_t box[2]     = {KT, TM};
    cuuint32_t es[2]      = {1, 1};
    enc(&tmA, CU_TENSOR_MAP_DATA_TYPE_FLOAT32, 2, xt_ptr, dims, strides, box,
        es, CU_TENSOR_MAP_INTERLEAVE_NONE, CU_TENSOR_MAP_SWIZZLE_128B,
        CU_TENSOR_MAP_L2_PROMOTION_L2_128B, CU_TENSOR_MAP_FLOAT_OOB_FILL_NONE);
  }
  {
    cuuint64_t dims[2]    = {(cuuint64_t)KDIM, (cuuint64_t)NDIM};
    cuuint64_t strides[1] = {(cuuint64_t)KDIM * sizeof(float)};
    cuuint32_t box[2]     = {KT, 32};    // one 32x32 n-block per TMA
    cuuint32_t es[2]      = {1, 1};
    enc(&tmB, CU_TENSOR_MAP_DATA_TYPE_FLOAT32, 2, wm_ptr, dims, strides, box,
        es, CU_TENSOR_MAP_INTERLEAVE_NONE, CU_TENSOR_MAP_SWIZZLE_128B,
        CU_TENSOR_MAP_L2_PROMOTION_L2_128B, CU_TENSOR_MAP_FLOAT_OOB_FILL_NONE);
  }

  // 3) GEMM: grid.x = n-tiles (16), grid.y = m-tiles (64)
  cudaFuncSetAttribute(bsl_gemm_kernel,
                       cudaFuncAttributeMaxDynamicSharedMemorySize, SMEM_TOTAL);
  dim3 grid(NDIM / TN, MDIM / TM);
  bsl_gemm_kernel<<<grid, THREADS, SMEM_TOTAL>>>(tmA, tmB, bias, (float*)d_out);
}

// round 7
// speedup vs baseline: 1.3224x; 1.0200x over previous
#include <cuda_runtime.h>
#include <cuda.h>
#include <cstdint>
#include <cstddef>

// Problem dims
#define MDIM 8192
#define NDIM 4096
#define KDIM 4096
#define BLK  32

// GEMM tiling
#define TM 128
#define TN 256
#define KT 32                 // fp32 elements per K-chunk = one K-block = 128B row
#define NSTAGES 4
#define NKITER (KDIM / KT)    // 128
#define NWC 16                // compute warps (2m x 8n, warp tile 64x32)
#define THREADS 544           // 16 compute warps + 1 producer warp

#define A_BYTES (TM * KT * 4)         // 16384
#define B_BYTES (TN * KT * 4)         // 32768
#define BBLK_BYTES (32 * KT * 4)      // 4096 per n-block
#define STAGE_BYTES (A_BYTES + B_BYTES)               // 49152
#define SMEM_DATA0 1024
#define SMEM_TOTAL (SMEM_DATA0 + NSTAGES * STAGE_BYTES)  // 197632

#define OFF_FULL(s)  (16 + (s) * 8)
#define OFF_EMPTY(s) (64 + (s) * 8)
#define OFF_LIVE     512              // 128 bytes: live mask per k-block

// Scratch (static device globals: allowed, no runtime alloc)
__device__ float g_wm[(size_t)NDIM * (size_t)KDIM];   // masked+tf32+permuted W
__device__ float g_xt[(size_t)MDIM * (size_t)KDIM];   // tf32+permuted x
__device__ unsigned char g_live[(NDIM / TN) * NKITER];  // [16][128]

// ---------------- device helpers ----------------

__device__ __forceinline__ uint32_t smem_u32(const void* p) {
  uint32_t r;
  asm("{ .reg .u64 t; cvta.to.shared.u64 t, %1; cvt.u32.u64 %0, t; }"
      : "=r"(r) : "l"(p));
  return r;
}
__device__ __forceinline__ void mbar_init(uint32_t a, uint32_t cnt) {
  asm volatile("mbarrier.init.shared::cta.b64 [%0], %1;"
               :: "r"(a), "r"(cnt) : "memory");
}
__device__ __forceinline__ void mbar_expect_tx(uint32_t a, uint32_t bytes) {
  asm volatile("mbarrier.arrive.expect_tx.shared::cta.b64 _, [%0], %1;"
               :: "r"(a), "r"(bytes) : "memory");
}
__device__ __forceinline__ void mbar_arrive(uint32_t a) {
  asm volatile("mbarrier.arrive.shared::cta.b64 _, [%0];"
               :: "r"(a) : "memory");
}
__device__ __forceinline__ void mbar_wait(uint32_t a, uint32_t parity) {
  asm volatile(
      "{\n\t.reg .pred P;\n\t"
      "WL%=:\n\t"
      "mbarrier.try_wait.parity.acquire.cta.shared::cta.b64 P, [%0], %1, 0x989680;\n\t"
      "@P bra WD%=;\n\t"
      "bra WL%=;\n\t"
      "WD%=:\n\t}"
      :: "r"(a), "r"(parity) : "memory");
}
__device__ __forceinline__ void tma_load_2d(uint32_t smem_dst, const void* map,
                                            int cx, int cy, uint32_t bar) {
  asm volatile(
      "cp.async.bulk.tensor.2d.shared::cta.global.tile.mbarrier::complete_tx::bytes "
      "[%0], [%1, {%2, %3}], [%4];"
      :: "r"(smem_dst), "l"(map), "r"(cx), "r"(cy), "r"(bar) : "memory");
}
__device__ __forceinline__ uint32_t f2tf32(float f) {
  uint32_t u;
  asm("cvt.rna.tf32.f32 %0, %1;" : "=r"(u) : "f"(f));
  return u;
}
__device__ __forceinline__ void lds64(uint32_t addr, uint32_t& x, uint32_t& y) {
  asm volatile("ld.shared.v2.u32 {%0, %1}, [%2];"
               : "=r"(x), "=r"(y) : "r"(addr));
}
__device__ __forceinline__ void mma_tf32(float* c, uint32_t a0, uint32_t a1,
                                         uint32_t a2, uint32_t a3,
                                         uint32_t b0, uint32_t b1) {
  asm volatile(
      "mma.sync.aligned.m16n8k8.row.col.f32.tf32.tf32.f32 "
      "{%0,%1,%2,%3}, {%4,%5,%6,%7}, {%8,%9}, {%0,%1,%2,%3};"
      : "+f"(c[0]), "+f"(c[1]), "+f"(c[2]), "+f"(c[3])
      : "r"(a0), "r"(a1), "r"(a2), "r"(a3), "r"(b0), "r"(b1));
}

// ---------------- column permutation ----------------
// Within each 32-col k-block (one 128B SMEM row), logical col c (ks=c>>3,
// j=c&7, c4=j&3, h=j>>2) is stored at byte offset:
//   off = (c4&1)*8 + ks*16 + (c4>>1)*64 + h*4
// Pair (c4, c4+4) is an aligned 8B LDS.64. c4 occupies bits {3,6}, ks bits
// {4,5}; the SW128 swizzle XOR (grp*16, bits {4,5,6}) never maps two half-warp
// lanes to the same bank slot -> conflict-free LDS.64 (verified R4: L1 69->43%).

__device__ __forceinline__ int perm_src_col(int p) {
  // inverse map: stored slot p (0..31) <- logical col
  int h  = p & 1;
  int c4 = ((p >> 1) & 1) | (((p >> 4) & 1) << 1);
  int ks = (p >> 2) & 3;
  return ks * 8 + c4 + 4 * h;
}

// ---------------- pre-pass kernels ----------------

// W: mask + tf32-round + permute. One thread per 32-col k-block (128B).
// Dead blocks are never TMA-loaded by the GEMM (producer skips them), so we
// skip both the read of W and the zero store entirely.
__global__ void __launch_bounds__(256)
premask_kernel(const float4* __restrict__ w, const int* __restrict__ bm,
               float* __restrict__ wm) {
  int t = blockIdx.x * 256 + threadIdx.x;     // block index over [NDIM][KDIM/32]
  int o  = t >> 7;                             // output row
  int kb = t & 127;                            // k-block
  if (bm[((o >> 5) << 7) + kb] == 0) return;
  const float4* src = w + (size_t)t * 8;
  uint4* dst = reinterpret_cast<uint4*>(wm) + (size_t)t * 8;
  float v[32];
  #pragma unroll
  for (int q = 0; q < 8; q++) {
    float4 f = src[q];
    v[q * 4 + 0] = f.x; v[q * 4 + 1] = f.y; v[q * 4 + 2] = f.z; v[q * 4 + 3] = f.w;
  }
  uint32_t ov[32];
  #pragma unroll
  for (int p = 0; p < 32; p++) ov[p] = f2tf32(v[perm_src_col(p)]);
  #pragma unroll
  for (int q = 0; q < 8; q++)
    dst[q] = make_uint4(ov[q * 4], ov[q * 4 + 1], ov[q * 4 + 2], ov[q * 4 + 3]);
}

// x: tf32-round + permute.
__global__ void __launch_bounds__(256)
cvtx_kernel(const float4* __restrict__ x, float* __restrict__ xt) {
  int t = blockIdx.x * 256 + threadIdx.x;
  const float4* src = x + (size_t)t * 8;
  uint4* dst = reinterpret_cast<uint4*>(xt) + (size_t)t * 8;
  float v[32];
  #pragma unroll
  for (int q = 0; q < 8; q++) {
    float4 f = src[q];
    v[q * 4 + 0] = f.x; v[q * 4 + 1] = f.y; v[q * 4 + 2] = f.z; v[q * 4 + 3] = f.w;
  }
  uint32_t ov[32];
  #pragma unroll
  for (int p = 0; p < 32; p++) ov[p] = f2tf32(v[perm_src_col(p)]);
  #pragma unroll
  for (int q = 0; q < 8; q++)
    dst[q] = make_uint4(ov[q * 4], ov[q * 4 + 1], ov[q * 4 + 2], ov[q * 4 + 3]);
}

// Live mask: per (n-tile cn, k-block kb), bit j = block (cn*8+j, kb) nonzero.
__global__ void __launch_bounds__(256)
livemask_kernel(const int* __restrict__ bm, unsigned char* __restrict__ lv) {
  int t = blockIdx.x * 256 + threadIdx.x;   // 0..2047
  int cn = t >> 7, kb = t & 127;
  unsigned b = 0;
  #pragma unroll
  for (int j = 0; j < 8; j++)
    b |= (bm[(cn * 8 + j) * 128 + kb] ? 1u : 0u) << j;
  lv[t] = (unsigned char)b;
}

// ---------------- GEMM ----------------
// CTA 128x256, 16 compute warps (2m x 8n grid of 64x32 warp tiles) + 1
// producer. Every consumer warp waits full / arrives empty EVERY round
// (parity waits are only sound if every waiter observes every phase — the R6
// dead-warp skip aliased parities and crashed). Dead warps skip only the work.
// Fragment loads are double-buffered across the 4 ks steps so each step's
// MMAs never sit on a fresh 29-cyc LDS chain.

__device__ __forceinline__ void lds_frag_a(uint32_t Ab, uint32_t cx,
                                           uint32_t* a) {
  #pragma unroll
  for (int mt = 0; mt < 4; mt++) {
    // rows grp and grp+8 of the 16-row m-tile; {a0,a2} and {a1,a3}
    lds64(Ab + mt * 2048 + cx,        a[mt * 4 + 0], a[mt * 4 + 2]);
    lds64(Ab + mt * 2048 + 1024 + cx, a[mt * 4 + 1], a[mt * 4 + 3]);
  }
}
__device__ __forceinline__ void lds_frag_b(uint32_t Bb, uint32_t cx,
                                           uint32_t* b) {
  #pragma unroll
  for (int nt = 0; nt < 4; nt++)
    lds64(Bb + nt * 1024 + cx, b[nt * 2], b[nt * 2 + 1]);
}

__device__ __forceinline__ void stage_mma(uint32_t Ab, uint32_t Bb,
                                          uint32_t xorb, float acc[4][4][4]) {
  uint32_t a[2][16], b[2][8];
  lds_frag_b(Bb, xorb, b[0]);
  lds_frag_a(Ab, xorb, a[0]);
  #pragma unroll
  for (int ks = 0; ks < 4; ks++) {
    const int cur = ks & 1, nxt = cur ^ 1;
    if (ks < 3) {
      const uint32_t cx = ((uint32_t)((ks + 1) << 4)) ^ xorb;
      lds_frag_b(Bb, cx, b[nxt]);
      lds_frag_a(Ab, cx, a[nxt]);
    }
    #pragma unroll
    for (int mt = 0; mt < 4; mt++)
      #pragma unroll
      for (int nt = 0; nt < 4; nt++)
        mma_tf32(acc[mt][nt], a[cur][mt * 4 + 0], a[cur][mt * 4 + 1],
                 a[cur][mt * 4 + 2], a[cur][mt * 4 + 3],
                 b[cur][nt * 2], b[cur][nt * 2 + 1]);
  }
}

__global__ void __launch_bounds__(THREADS, 1)
bsl_gemm_kernel(const __grid_constant__ CUtensorMap tmA,
                const __grid_constant__ CUtensorMap tmB,
                const float* __restrict__ bias,
                float* __restrict__ out) {
  extern __shared__ char smem[];
  const uint32_t sb = smem_u32(smem);
  const int tid  = threadIdx.x;
  const int w    = tid >> 5;
  const int lane = tid & 31;
  const int grp  = lane >> 2;
  const int c4   = lane & 3;

  // grid: x = n-tile (16), y = m-tile (64)  -> wave-blocked for L2 reuse
  const int n0 = blockIdx.x * TN;
  const int m0 = blockIdx.y * TM;

  if (tid == 0) {
    #pragma unroll
    for (int s = 0; s < NSTAGES; s++) {
      mbar_init(sb + OFF_FULL(s), 1);
      mbar_init(sb + OFF_EMPTY(s), NWC);
    }
    asm volatile("fence.proxy.async.shared::cta;" ::: "memory");
  }
  if (tid < 32) {
    reinterpret_cast<uint32_t*>(smem + OFF_LIVE)[tid] =
        reinterpret_cast<const uint32_t*>(g_live)[blockIdx.x * 32 + tid];
  }
  __syncthreads();

  const unsigned char* lv = reinterpret_cast<const unsigned char*>(smem + OFF_LIVE);

  if (w == NWC) {
    // -------- producer warp --------
    if (lane == 0) {
      for (int kb = 0; kb < NKITER; kb++) {
        const int st = kb & (NSTAGES - 1);
        if (kb >= NSTAGES) mbar_wait(sb + OFF_EMPTY(st), ((kb - NSTAGES) >> 2) & 1);
        const unsigned L = lv[kb];
        const uint32_t tx = (L ? A_BYTES : 0u) + (uint32_t)__popc(L) * BBLK_BYTES;
        mbar_expect_tx(sb + OFF_FULL(st), tx);
        const uint32_t dst = sb + SMEM_DATA0 + st * STAGE_BYTES;
        if (L) tma_load_2d(dst, &tmA, kb * KT, m0, sb + OFF_FULL(st));
        #pragma unroll
        for (int j = 0; j < 8; j++)
          if ((L >> j) & 1)
            tma_load_2d(dst + A_BYTES + j * BBLK_BYTES, &tmB, kb * KT,
                        n0 + j * 32, sb + OFF_FULL(st));
      }
    }
    return;
  }

  // -------- compute warps: 2m x 8n, warp tile 64x32 (one n-block) --------
  const int wm_ = (w >> 3) * 64;     // warp m offset (0 or 64)
  const int j0  = w & 7;             // the warp's n-block
  const int wn_ = j0 * 32;           // warp n offset

  const uint32_t arow0 = (uint32_t)((wm_ + grp) * 128);
  const uint32_t brow0 = (uint32_t)(j0 * BBLK_BYTES + grp * 128);
  // c4 -> bits {3,6}; swizzle XOR grp -> bits {4,5,6}; ks added as bits {4,5}.
  const uint32_t xorb =
      (((uint32_t)(c4 & 1) << 3) | ((uint32_t)(c4 >> 1) << 6)) ^
      ((uint32_t)grp << 4);

  float acc[4][4][4];
  #pragma unroll
  for (int mt = 0; mt < 4; mt++)
    #pragma unroll
    for (int nt = 0; nt < 4; nt++)
      #pragma unroll
      for (int r = 0; r < 4; r++) acc[mt][nt][r] = 0.f;

  for (int kb = 0; kb < NKITER; kb++) {
    const int st = kb & (NSTAGES - 1);
    mbar_wait(sb + OFF_FULL(st), (kb >> 2) & 1);
    if ((lv[kb] >> j0) & 1) {
      const uint32_t base = sb + SMEM_DATA0 + st * STAGE_BYTES;
      stage_mma(base + arow0, base + A_BYTES + brow0, xorb, acc);
    }
    if (lane == 0) mbar_arrive(sb + OFF_EMPTY(st));
  }

  // -------- epilogue --------
  #pragma unroll
  for (int nt = 0; nt < 4; nt++) {
    const int col = n0 + wn_ + nt * 8 + c4 * 2;
    const float2 bv = *reinterpret_cast<const float2*>(bias + col);
    #pragma unroll
    for (int mt = 0; mt < 4; mt++) {
      const int row = m0 + wm_ + mt * 16 + grp;
      float2 o0, o1;
      o0.x = acc[mt][nt][0] + bv.x;
      o0.y = acc[mt][nt][1] + bv.y;
      o1.x = acc[mt][nt][2] + bv.x;
      o1.y = acc[mt][nt][3] + bv.y;
      *reinterpret_cast<float2*>(out + (size_t)row * NDIM + col) = o0;
      *reinterpret_cast<float2*>(out + (size_t)(row + 8) * NDIM + col) = o1;
    }
  }
}

// ---------------- host launch ----------------

typedef CUresult (*EncodeTiledFn)(
    CUtensorMap*, CUtensorMapDataType, cuuint32_t, void*, const cuuint64_t*,
    const cuuint64_t*, const cuuint32_t*, const cuuint32_t*,
    CUtensorMapInterleave, CUtensorMapSwizzle, CUtensorMapL2promotion,
    CUtensorMapFloatOOBfill);

extern "C" void kernel_launch(void* const* d_in, const int* in_sizes, int n_in,
                              void* d_out, int out_size) {
  const float* x = nullptr;
  const float* wgt = nullptr;
  const float* bias = nullptr;
  const int* bm = nullptr;
  for (int i = 0; i < n_in; i++) {
    long long sz = in_sizes[i];
    if (sz == (long long)MDIM * KDIM)       x    = (const float*)d_in[i];
    else if (sz == (long long)NDIM * KDIM)  wgt  = (const float*)d_in[i];
    else if (sz == NDIM)                    bias = (const float*)d_in[i];
    else if (sz == (NDIM / BLK) * (KDIM / BLK)) bm = (const int*)d_in[i];
  }

  void* wm_ptr = nullptr;
  void* xt_ptr = nullptr;
  void* lv_ptr = nullptr;
  cudaGetSymbolAddress(&wm_ptr, g_wm);
  cudaGetSymbolAddress(&xt_ptr, g_xt);
  cudaGetSymbolAddress(&lv_ptr, g_live);

  // 1) Pre-pass (one thread per 32-col k-block)
  premask_kernel<<<(NDIM * (KDIM / 32)) / 256, 256>>>(
      (const float4*)wgt, bm, (float*)wm_ptr);
  cvtx_kernel<<<(int)(((size_t)MDIM * (KDIM / 32)) / 256), 256>>>(
      (const float4*)x, (float*)xt_ptr);
  livemask_kernel<<<8, 256>>>(bm, (unsigned char*)lv_ptr);

  // 2) TMA descriptors
  EncodeTiledFn enc = nullptr;
  cudaDriverEntryPointQueryResult qr;
  cudaGetDriverEntryPoint("cuTensorMapEncodeTiled", (void**)&enc,
                          cudaEnableDefault, &qr);

  CUtensorMap tmA, tmB;
  {
    cuuint64_t dims[2]    = {(cuuint64_t)KDIM, (cuuint64_t)MDIM};
    cuuint64_t strides[1] = {(cuuint64_t)KDIM * sizeof(float)};
    cuuint32_t box[2]     = {KT, TM};
    cuuint32_t es[2]      = {1, 1};
    enc(&tmA, CU_TENSOR_MAP_DATA_TYPE_FLOAT32, 2, xt_ptr, dims, strides, box,
        es, CU_TENSOR_MAP_INTERLEAVE_NONE, CU_TENSOR_MAP_SWIZZLE_128B,
        CU_TENSOR_MAP_L2_PROMOTION_L2_128B, CU_TENSOR_MAP_FLOAT_OOB_FILL_NONE);
  }
  {
    cuuint64_t dims[2]    = {(cuuint64_t)KDIM, (cuuint64_t)NDIM};
    cuuint64_t strides[1] = {(cuuint64_t)KDIM * sizeof(float)};
    cuuint32_t box[2]     = {KT, 32};    // one 32x32 n-block per TMA
    cuuint32_t es[2]      = {1, 1};
    enc(&tmB, CU_TENSOR_MAP_DATA_TYPE_FLOAT32, 2, wm_ptr, dims, strides, box,
        es, CU_TENSOR_MAP_INTERLEAVE_NONE, CU_TENSOR_MAP_SWIZZLE_128B,
        CU_TENSOR_MAP_L2_PROMOTION_L2_128B, CU_TENSOR_MAP_FLOAT_OOB_FILL_NONE);
  }

  // 3) GEMM: grid.x = n-tiles (16), grid.y = m-tiles (64)
  cudaFuncSetAttribute(bsl_gemm_kernel,
                       cudaFuncAttributeMaxDynamicSharedMemorySize, SMEM_TOTAL);
  dim3 grid(NDIM / TN, MDIM / TM);
  bsl_gemm_kernel<<<grid, THREADS, SMEM_TOTAL>>>(tmA, tmB, bias, (float*)d_out);
}

// round 8
// speedup vs baseline: 1.4234x; 1.0764x over previous
#include <cuda_runtime.h>
#include <cuda.h>
#include <cstdint>
#include <cstddef>

// Problem dims
#define MDIM 8192
#define NDIM 4096
#define KDIM 4096
#define BLK  32

// GEMM tiling
#define TM 128
#define TN 256
#define KT 32                 // fp32 elements per K-chunk = one K-block = 128B row
#define NSTAGES 4
#define NKITER (KDIM / KT)    // 128
#define NWC 16                // compute warps (2m x 8n, warp tile 64x32)
#define THREADS 544           // 16 compute warps + 1 producer warp

#define A_BYTES (TM * KT * 4)         // 16384
#define B_BYTES (TN * KT * 4)         // 32768
#define BBLK_BYTES (32 * KT * 4)      // 4096 per n-block
#define STAGE_BYTES (A_BYTES + B_BYTES)               // 49152
#define SMEM_DATA0 1024
#define SMEM_TOTAL (SMEM_DATA0 + NSTAGES * STAGE_BYTES)  // 197632

#define OFF_FULL(s)  (16 + (s) * 8)
#define OFF_EMPTY(s) (64 + (s) * 8)
#define OFF_LIVE     512              // 128 bytes: live mask per k-block

// Scratch (static device globals: allowed, no runtime alloc)
__device__ float g_wm[(size_t)NDIM * (size_t)KDIM];   // masked+tf32+permuted W
__device__ float g_xt[(size_t)MDIM * (size_t)KDIM];   // tf32+permuted x
__device__ unsigned char g_live[(NDIM / TN) * NKITER];  // [16][128]

// ---------------- device helpers ----------------

__device__ __forceinline__ uint32_t smem_u32(const void* p) {
  uint32_t r;
  asm("{ .reg .u64 t; cvta.to.shared.u64 t, %1; cvt.u32.u64 %0, t; }"
      : "=r"(r) : "l"(p));
  return r;
}
__device__ __forceinline__ void mbar_init(uint32_t a, uint32_t cnt) {
  asm volatile("mbarrier.init.shared::cta.b64 [%0], %1;"
               :: "r"(a), "r"(cnt) : "memory");
}
__device__ __forceinline__ void mbar_expect_tx(uint32_t a, uint32_t bytes) {
  asm volatile("mbarrier.arrive.expect_tx.shared::cta.b64 _, [%0], %1;"
               :: "r"(a), "r"(bytes) : "memory");
}
__device__ __forceinline__ void mbar_arrive(uint32_t a) {
  asm volatile("mbarrier.arrive.shared::cta.b64 _, [%0];"
               :: "r"(a) : "memory");
}
__device__ __forceinline__ void mbar_wait(uint32_t a, uint32_t parity) {
  asm volatile(
      "{\n\t.reg .pred P;\n\t"
      "WL%=:\n\t"
      "mbarrier.try_wait.parity.acquire.cta.shared::cta.b64 P, [%0], %1, 0x989680;\n\t"
      "@P bra WD%=;\n\t"
      "bra WL%=;\n\t"
      "WD%=:\n\t}"
      :: "r"(a), "r"(parity) : "memory");
}
__device__ __forceinline__ void tma_load_2d(uint32_t smem_dst, const void* map,
                                            int cx, int cy, uint32_t bar) {
  asm volatile(
      "cp.async.bulk.tensor.2d.shared::cta.global.tile.mbarrier::complete_tx::bytes "
      "[%0], [%1, {%2, %3}], [%4];"
      :: "r"(smem_dst), "l"(map), "r"(cx), "r"(cy), "r"(bar) : "memory");
}
__device__ __forceinline__ uint32_t f2tf32(float f) {
  uint32_t u;
  asm("cvt.rna.tf32.f32 %0, %1;" : "=r"(u) : "f"(f));
  return u;
}
__device__ __forceinline__ void lds64(uint32_t addr, uint32_t& x, uint32_t& y) {
  asm volatile("ld.shared.v2.u32 {%0, %1}, [%2];"
               : "=r"(x), "=r"(y) : "r"(addr));
}
__device__ __forceinline__ void mma_tf32(float* c, uint32_t a0, uint32_t a1,
                                         uint32_t a2, uint32_t a3,
                                         uint32_t b0, uint32_t b1) {
  asm volatile(
      "mma.sync.aligned.m16n8k8.row.col.f32.tf32.tf32.f32 "
      "{%0,%1,%2,%3}, {%4,%5,%6,%7}, {%8,%9}, {%0,%1,%2,%3};"
      : "+f"(c[0]), "+f"(c[1]), "+f"(c[2]), "+f"(c[3])
      : "r"(a0), "r"(a1), "r"(a2), "r"(a3), "r"(b0), "r"(b1));
}

// ---------------- column permutation ----------------
// Within each 32-col k-block (one 128B SMEM row), logical col c (ks=c>>3,
// j=c&7, c4=j&3, h=j>>2) is stored at byte offset:
//   off = (c4&1)*8 + ks*16 + (c4>>1)*64 + h*4
// Pair (c4, c4+4) is an aligned 8B LDS.64. c4 occupies bits {3,6}, ks bits
// {4,5}; the SW128 swizzle XOR (grp*16, bits {4,5,6}) never maps two half-warp
// lanes to the same bank slot -> conflict-free LDS.64 (verified R4: L1 69->43%).

__device__ __forceinline__ int perm_src_col(int p) {
  // inverse map: stored slot p (0..31) <- logical col
  int h  = p & 1;
  int c4 = ((p >> 1) & 1) | (((p >> 4) & 1) << 1);
  int ks = (p >> 2) & 3;
  return ks * 8 + c4 + 4 * h;
}

// ---------------- pre-pass kernels ----------------

// W: mask + tf32-round + permute. One thread per 32-col k-block (128B).
// Dead blocks are never TMA-loaded by the GEMM (producer skips them).
__global__ void __launch_bounds__(256)
premask_kernel(const float4* __restrict__ w, const int* __restrict__ bm,
               float* __restrict__ wm) {
  int t = blockIdx.x * 256 + threadIdx.x;     // block index over [NDIM][KDIM/32]
  int o  = t >> 7;                             // output row
  int kb = t & 127;                            // k-block
  if (bm[((o >> 5) << 7) + kb] == 0) return;
  const float4* src = w + (size_t)t * 8;
  uint4* dst = reinterpret_cast<uint4*>(wm) + (size_t)t * 8;
  float v[32];
  #pragma unroll
  for (int q = 0; q < 8; q++) {
    float4 f = src[q];
    v[q * 4 + 0] = f.x; v[q * 4 + 1] = f.y; v[q * 4 + 2] = f.z; v[q * 4 + 3] = f.w;
  }
  uint32_t ov[32];
  #pragma unroll
  for (int p = 0; p < 32; p++) ov[p] = f2tf32(v[perm_src_col(p)]);
  #pragma unroll
  for (int q = 0; q < 8; q++)
    dst[q] = make_uint4(ov[q * 4], ov[q * 4 + 1], ov[q * 4 + 2], ov[q * 4 + 3]);
}

// x: tf32-round + permute.
__global__ void __launch_bounds__(256)
cvtx_kernel(const float4* __restrict__ x, float* __restrict__ xt) {
  int t = blockIdx.x * 256 + threadIdx.x;
  const float4* src = x + (size_t)t * 8;
  uint4* dst = reinterpret_cast<uint4*>(xt) + (size_t)t * 8;
  float v[32];
  #pragma unroll
  for (int q = 0; q < 8; q++) {
    float4 f = src[q];
    v[q * 4 + 0] = f.x; v[q * 4 + 1] = f.y; v[q * 4 + 2] = f.z; v[q * 4 + 3] = f.w;
  }
  uint32_t ov[32];
  #pragma unroll
  for (int p = 0; p < 32; p++) ov[p] = f2tf32(v[perm_src_col(p)]);
  #pragma unroll
  for (int q = 0; q < 8; q++)
    dst[q] = make_uint4(ov[q * 4], ov[q * 4 + 1], ov[q * 4 + 2], ov[q * 4 + 3]);
}

// Live mask: per (n-tile cn, k-block kb), bit j = block (cn*8+j, kb) nonzero.
__global__ void __launch_bounds__(256)
livemask_kernel(const int* __restrict__ bm, unsigned char* __restrict__ lv) {
  int t = blockIdx.x * 256 + threadIdx.x;   // 0..2047
  int cn = t >> 7, kb = t & 127;
  unsigned b = 0;
  #pragma unroll
  for (int j = 0; j < 8; j++)
    b |= (bm[(cn * 8 + j) * 128 + kb] ? 1u : 0u) << j;
  lv[t] = (unsigned char)b;
}

// ---------------- GEMM ----------------
// CTA 128x256, 16 compute warps + 1 producer. Every consumer warp waits full /
// arrives empty every round (parity soundness). Dead warps skip only the work.
//
// Warp->n-block map: j0 = w>>1, m-half = w&1. SMSP = w%4, so each SMSP hosts
// 4 DISTINCT n-blocks ({0,2,4,6} or {1,3,5,7}); per-round SMSP live load is
// Bin(4,1/2) instead of the old j0=w&7 map's 2*Bin(2,1/2) (SMSP0 held blocks
// {0,4,0,4}). E[max SMSP load] drops 3.36 -> 2.55 warp-equivalents, directly
// cutting the per-round gating term.

__device__ __forceinline__ void lds_frag_a(uint32_t Ab, uint32_t cx,
                                           uint32_t* a) {
  #pragma unroll
  for (int mt = 0; mt < 4; mt++) {
    lds64(Ab + mt * 2048 + cx,        a[mt * 4 + 0], a[mt * 4 + 2]);
    lds64(Ab + mt * 2048 + 1024 + cx, a[mt * 4 + 1], a[mt * 4 + 3]);
  }
}
__device__ __forceinline__ void lds_frag_b(uint32_t Bb, uint32_t cx,
                                           uint32_t* b) {
  #pragma unroll
  for (int nt = 0; nt < 4; nt++)
    lds64(Bb + nt * 1024 + cx, b[nt * 2], b[nt * 2 + 1]);
}

__device__ __forceinline__ void stage_mma(uint32_t Ab, uint32_t Bb,
                                          const uint32_t* cxs,
                                          float acc[4][4][4]) {
  uint32_t a[2][16], b[2][8];
  lds_frag_b(Bb, cxs[0], b[0]);
  lds_frag_a(Ab, cxs[0], a[0]);
  #pragma unroll
  for (int ks = 0; ks < 4; ks++) {
    const int cur = ks & 1, nxt = cur ^ 1;
    if (ks < 3) {
      lds_frag_b(Bb, cxs[ks + 1], b[nxt]);
      lds_frag_a(Ab, cxs[ks + 1], a[nxt]);
    }
    #pragma unroll
    for (int mt = 0; mt < 4; mt++)
      #pragma unroll
      for (int nt = 0; nt < 4; nt++)
        mma_tf32(acc[mt][nt], a[cur][mt * 4 + 0], a[cur][mt * 4 + 1],
                 a[cur][mt * 4 + 2], a[cur][mt * 4 + 3],
                 b[cur][nt * 2], b[cur][nt * 2 + 1]);
  }
}

__global__ void __launch_bounds__(THREADS, 1)
bsl_gemm_kernel(const __grid_constant__ CUtensorMap tmA,
                const __grid_constant__ CUtensorMap tmB,
                const float* __restrict__ bias,
                float* __restrict__ out) {
  extern __shared__ char smem[];
  const uint32_t sb = smem_u32(smem);
  const int tid  = threadIdx.x;
  const int w    = tid >> 5;
  const int lane = tid & 31;
  const int grp  = lane >> 2;
  const int c4   = lane & 3;

  // grid: x = n-tile (16), y = m-tile (64)  -> wave-blocked for L2 reuse
  const int n0 = blockIdx.x * TN;
  const int m0 = blockIdx.y * TM;

  if (tid == 0) {
    #pragma unroll
    for (int s = 0; s < NSTAGES; s++) {
      mbar_init(sb + OFF_FULL(s), 1);
      mbar_init(sb + OFF_EMPTY(s), NWC);
    }
    asm volatile("fence.proxy.async.shared::cta;" ::: "memory");
  }
  if (tid < 32) {
    reinterpret_cast<uint32_t*>(smem + OFF_LIVE)[tid] =
        reinterpret_cast<const uint32_t*>(g_live)[blockIdx.x * 32 + tid];
  }
  __syncthreads();

  const unsigned char* lv = reinterpret_cast<const unsigned char*>(smem + OFF_LIVE);

  if (w == NWC) {
    // -------- producer warp --------
    if (lane == 0) {
      for (int kb = 0; kb < NKITER; kb++) {
        const int st = kb & (NSTAGES - 1);
        if (kb >= NSTAGES) mbar_wait(sb + OFF_EMPTY(st), ((kb - NSTAGES) >> 2) & 1);
        const unsigned L = lv[kb];
        const uint32_t tx = (L ? A_BYTES : 0u) + (uint32_t)__popc(L) * BBLK_BYTES;
        mbar_expect_tx(sb + OFF_FULL(st), tx);
        const uint32_t dst = sb + SMEM_DATA0 + st * STAGE_BYTES;
        if (L) tma_load_2d(dst, &tmA, kb * KT, m0, sb + OFF_FULL(st));
        #pragma unroll
        for (int j = 0; j < 8; j++)
          if ((L >> j) & 1)
            tma_load_2d(dst + A_BYTES + j * BBLK_BYTES, &tmB, kb * KT,
                        n0 + j * 32, sb + OFF_FULL(st));
      }
    }
    return;
  }

  // -------- compute warps: j0 = w>>1 (SMSP-balanced), m-half = w&1 --------
  const int j0  = w >> 1;            // the warp's n-block (0..7)
  const int wm_ = (w & 1) * 64;      // warp m offset (0 or 64)
  const int wn_ = j0 * 32;           // warp n offset

  const uint32_t arow0 = (uint32_t)((wm_ + grp) * 128);
  const uint32_t brow0 = (uint32_t)(j0 * BBLK_BYTES + grp * 128);
  // c4 -> bits {3,6}; swizzle XOR grp -> bits {4,5,6}; ks added as bits {4,5}.
  const uint32_t xorb =
      (((uint32_t)(c4 & 1) << 3) | ((uint32_t)(c4 >> 1) << 6)) ^
      ((uint32_t)grp << 4);
  uint32_t cxs[4];
  #pragma unroll
  for (int ks = 0; ks < 4; ks++) cxs[ks] = ((uint32_t)(ks << 4)) ^ xorb;

  float acc[4][4][4];
  #pragma unroll
  for (int mt = 0; mt < 4; mt++)
    #pragma unroll
    for (int nt = 0; nt < 4; nt++)
      #pragma unroll
      for (int r = 0; r < 4; r++) acc[mt][nt][r] = 0.f;

  for (int kb = 0; kb < NKITER; kb++) {
    const int st = kb & (NSTAGES - 1);
    mbar_wait(sb + OFF_FULL(st), (kb >> 2) & 1);
    if ((lv[kb] >> j0) & 1) {
      const uint32_t base = sb + SMEM_DATA0 + st * STAGE_BYTES;
      stage_mma(base + arow0, base + A_BYTES + brow0, cxs, acc);
    }
    if (lane == 0) mbar_arrive(sb + OFF_EMPTY(st));
  }

  // -------- epilogue --------
  #pragma unroll
  for (int nt = 0; nt < 4; nt++) {
    const int col = n0 + wn_ + nt * 8 + c4 * 2;
    const float2 bv = *reinterpret_cast<const float2*>(bias + col);
    #pragma unroll
    for (int mt = 0; mt < 4; mt++) {
      const int row = m0 + wm_ + mt * 16 + grp;
      float2 o0, o1;
      o0.x = acc[mt][nt][0] + bv.x;
      o0.y = acc[mt][nt][1] + bv.y;
      o1.x = acc[mt][nt][2] + bv.x;
      o1.y = acc[mt][nt][3] + bv.y;
      *reinterpret_cast<float2*>(out + (size_t)row * NDIM + col) = o0;
      *reinterpret_cast<float2*>(out + (size_t)(row + 8) * NDIM + col) = o1;
    }
  }
}

// ---------------- host launch ----------------

typedef CUresult (*EncodeTiledFn)(
    CUtensorMap*, CUtensorMapDataType, cuuint32_t, void*, const cuuint64_t*,
    const cuuint64_t*, const cuuint32_t*, const cuuint32_t*,
    CUtensorMapInterleave, CUtensorMapSwizzle, CUtensorMapL2promotion,
    CUtensorMapFloatOOBfill);

extern "C" void kernel_launch(void* const* d_in, const int* in_sizes, int n_in,
                              void* d_out, int out_size) {
  const float* x = nullptr;
  const float* wgt = nullptr;
  const float* bias = nullptr;
  const int* bm = nullptr;
  for (int i = 0; i < n_in; i++) {
    long long sz = in_sizes[i];
    if (sz == (long long)MDIM * KDIM)       x    = (const float*)d_in[i];
    else if (sz == (long long)NDIM * KDIM)  wgt  = (const float*)d_in[i];
    else if (sz == NDIM)                    bias = (const float*)d_in[i];
    else if (sz == (NDIM / BLK) * (KDIM / BLK)) bm = (const int*)d_in[i];
  }

  void* wm_ptr = nullptr;
  void* xt_ptr = nullptr;
  void* lv_ptr = nullptr;
  cudaGetSymbolAddress(&wm_ptr, g_wm);
  cudaGetSymbolAddress(&xt_ptr, g_xt);
  cudaGetSymbolAddress(&lv_ptr, g_live);

  // 1) Pre-pass (one thread per 32-col k-block)
  premask_kernel<<<(NDIM * (KDIM / 32)) / 256, 256>>>(
      (const float4*)wgt, bm, (float*)wm_ptr);
  cvtx_kernel<<<(int)(((size_t)MDIM * (KDIM / 32)) / 256), 256>>>(
      (const float4*)x, (float*)xt_ptr);
  livemask_kernel<<<8, 256>>>(bm, (unsigned char*)lv_ptr);

  // 2) TMA descriptors
  EncodeTiledFn enc = nullptr;
  cudaDriverEntryPointQueryResult qr;
  cudaGetDriverEntryPoint("cuTensorMapEncodeTiled", (void**)&enc,
                          cudaEnableDefault, &qr);

  CUtensorMap tmA, tmB;
  {
    cuuint64_t dims[2]    = {(cuuint64_t)KDIM, (cuuint64_t)MDIM};
    cuuint64_t strides[1] = {(cuuint64_t)KDIM * sizeof(float)};
    cuuint32_t box[2]     = {KT, TM};
    cuuint32_t es[2]      = {1, 1};
    enc(&tmA, CU_TENSOR_MAP_DATA_TYPE_FLOAT32, 2, xt_ptr, dims, strides, box,
        es, CU_TENSOR_MAP_INTERLEAVE_NONE, CU_TENSOR_MAP_SWIZZLE_128B,
        CU_TENSOR_MAP_L2_PROMOTION_L2_128B, CU_TENSOR_MAP_FLOAT_OOB_FILL_NONE);
  }
  {
    cuuint64_t dims[2]    = {(cuuint64_t)KDIM, (cuuint64_t)NDIM};
    cuuint64_t strides[1] = {(cuuint64_t)KDIM * sizeof(float)};
    cuuint32_t box[2]     = {KT, 32};    // one 32x32 n-block per TMA
    cuuint32_t es[2]      = {1, 1};
    enc(&tmB, CU_TENSOR_MAP_DATA_TYPE_FLOAT32, 2, wm_ptr, dims, strides, box,
        es, CU_TENSOR_MAP_INTERLEAVE_NONE, CU_TENSOR_MAP_SWIZZLE_128B,
        CU_TENSOR_MAP_L2_PROMOTION_L2_128B, CU_TENSOR_MAP_FLOAT_OOB_FILL_NONE);
  }

  // 3) GEMM: grid.x = n-tiles (16), grid.y = m-tiles (64)
  cudaFuncSetAttribute(bsl_gemm_kernel,
                       cudaFuncAttributeMaxDynamicSharedMemorySize, SMEM_TOTAL);
  dim3 grid(NDIM / TN, MDIM / TM);
  bsl_gemm_kernel<<<grid, THREADS, SMEM_TOTAL>>>(tmA, tmB, bias, (float*)d_out);
}